// round 8
// baseline (speedup 1.0000x reference)
#include <cuda_runtime.h>
#include <cuda_bf16.h>
#include <cuda_fp16.h>
#include <math.h>
#include <stdint.h>

// Problem constants (fixed by the dataset)
#define N_NODES   100000
#define N_EDGES   1600000
#define IN_F      256
#define OUT_F     256
#define D_LABEL   32
#define ALPHA     0.2f
#define EPS_RS    1e-9f

#define SCAN_BLK  512

// Scratch (device globals: allowed; no cudaMalloc anywhere)
__device__ __half g_Wh_h[(size_t)N_NODES * OUT_F];   // ~50 MB (fp16 Wh)
__device__ float g_att[N_EDGES];
__device__ int   g_deg[N_NODES];
__device__ int   g_rowstart[N_NODES];
__device__ int   g_cursor[N_NODES];
__device__ int   g_edst[N_EDGES];
__device__ int   g_bsum[256];
// W transposed + bf16 split: Wt[n][k] = W[k][n]
__device__ __nv_bfloat16 g_Wt_hi[256 * 256];
__device__ __nv_bfloat16 g_Wt_lo[256 * 256];

// ---------------------------------------------------------------------------
// helpers
// ---------------------------------------------------------------------------
__device__ __forceinline__ uint32_t smem_u32(const void* p) {
    uint32_t a;
    asm("{ .reg .u64 t; cvta.to.shared.u64 t, %1; cvt.u32.u64 %0, t; }"
        : "=r"(a) : "l"(p));
    return a;
}

__device__ __forceinline__ void ldsm_x4(uint32_t* r, uint32_t addr) {
    asm volatile("ldmatrix.sync.aligned.m8n8.x4.shared.b16 {%0,%1,%2,%3}, [%4];"
                 : "=r"(r[0]), "=r"(r[1]), "=r"(r[2]), "=r"(r[3]) : "r"(addr));
}
__device__ __forceinline__ void ldsm_x2(uint32_t* r, uint32_t addr) {
    asm volatile("ldmatrix.sync.aligned.m8n8.x2.shared.b16 {%0,%1}, [%2];"
                 : "=r"(r[0]), "=r"(r[1]) : "r"(addr));
}
__device__ __forceinline__ void mma_bf16(float* c, const uint32_t* a, const uint32_t* b) {
    asm volatile(
        "mma.sync.aligned.m16n8k16.row.col.f32.bf16.bf16.f32 "
        "{%0,%1,%2,%3}, {%4,%5,%6,%7}, {%8,%9}, {%0,%1,%2,%3};"
        : "+f"(c[0]), "+f"(c[1]), "+f"(c[2]), "+f"(c[3])
        : "r"(a[0]), "r"(a[1]), "r"(a[2]), "r"(a[3]), "r"(b[0]), "r"(b[1]));
}

// ---------------------------------------------------------------------------
// Kernel 0: zero degree array
// ---------------------------------------------------------------------------
__global__ void k_zero_deg(int n) {
    int i = blockIdx.x * blockDim.x + threadIdx.x;
    if (i < n) g_deg[i] = 0;
}

// ---------------------------------------------------------------------------
// Kernel P: W [K,N] fp32 -> Wt_hi/Wt_lo [N,K] bf16 split
// ---------------------------------------------------------------------------
__global__ void k_prep_W(const float* __restrict__ W) {
    int i = blockIdx.x * 256 + threadIdx.x;     // 0..65535
    int n = i >> 8, k = i & 255;
    float w = W[k * 256 + n];
    __nv_bfloat16 hi = __float2bfloat16(w);
    __nv_bfloat16 lo = __float2bfloat16(w - __bfloat162float(hi));
    g_Wt_hi[n * 256 + k] = hi;
    g_Wt_lo[n * 256 + k] = lo;
}

// ---------------------------------------------------------------------------
// Kernel 1: HMMA GEMM  Wh = h @ W  via bf16 hi/lo split (3 products)
// R8 retile: CTA 128M x 64N, 256 thr, warp grid 4x2, warp tile 32x32.
// smem ~106KB, 2 CTAs/SM (__launch_bounds__(256,2)).
// ---------------------------------------------------------------------------
#define B_ROW 528
#define A_ROW 80
#define SM_BH 0                 // 64 * 528 = 33792
#define SM_BL 33792
#define SM_A0 67584
#define A_STAGE 20480           // hi 10240 + lo 10240
#define SM_AL_OFF 10240
#define GSM_TOTAL 108544        // 67584 + 2*20480

__global__ __launch_bounds__(256, 2) void k_gemm_mma(const float* __restrict__ A, int M)
{
    extern __shared__ __align__(16) char sm[];
    const uint32_t sbase = smem_u32(sm);
    const int tid  = threadIdx.x;
    const int lane = tid & 31;
    const int wid  = tid >> 5;
    const int wm   = wid >> 1;          // 0..3
    const int wn   = wid & 1;           // 0..1
    const int rowBase = blockIdx.y * 128;
    const int colBase = blockIdx.x * 64;

    // ---- stage B (hi+lo, full K, 64 cols) into smem
    {
        const char* srcH = (const char*)(g_Wt_hi + (size_t)colBase * 256);
        const char* srcL = (const char*)(g_Wt_lo + (size_t)colBase * 256);
        for (int i = tid; i < 64 * 32; i += 256) {
            int n = i >> 5, c = i & 31;
            *(uint4*)(sm + SM_BH + n * B_ROW + c * 16) =
                *(const uint4*)(srcH + n * 512 + c * 16);
            *(uint4*)(sm + SM_BL + n * B_ROW + c * 16) =
                *(const uint4*)(srcL + n * 512 + c * 16);
        }
    }

    float acc[2][4][4];
#pragma unroll
    for (int i = 0; i < 2; i++)
#pragma unroll
        for (int j = 0; j < 4; j++)
#pragma unroll
            for (int q = 0; q < 4; q++) acc[i][j][q] = 0.0f;

    const int ar   = tid >> 1;
    const int ahlf = tid & 1;
    const int grow = rowBase + ar;
    const float* aptr = A + (size_t)grow * IN_F + ahlf * 16;

    float4 pf[4];
#pragma unroll
    for (int q = 0; q < 4; q++) pf[q] = make_float4(0.f, 0.f, 0.f, 0.f);
    if (grow < M) {
#pragma unroll
        for (int q = 0; q < 4; q++) pf[q] = *(const float4*)(aptr + q * 4);
    }

    const uint32_t a_frag_off = (uint32_t)((wm * 32 + (lane & 15)) * A_ROW + (lane >> 4) * 16);
    const int bl_ = lane & 15;
    const uint32_t b_frag_off = (uint32_t)((wn * 32 + (bl_ & 7)) * B_ROW + ((bl_ >> 3) & 1) * 16);
    const uint32_t sts_off = (uint32_t)(ar * A_ROW + ahlf * 32);

    for (int c = 0; c < 8; c++) {
        const int stage = c & 1;
        // convert pf (16 f32) -> bf16 hi/lo, store to smem stage
        {
            uint32_t hv[8], lv[8];
#pragma unroll
            for (int q = 0; q < 4; q++) {
                float x[4] = { pf[q].x, pf[q].y, pf[q].z, pf[q].w };
#pragma unroll
                for (int e = 0; e < 2; e++) {
                    float f0 = x[e * 2], f1 = x[e * 2 + 1];
                    __nv_bfloat16 h0 = __float2bfloat16(f0);
                    __nv_bfloat16 h1 = __float2bfloat16(f1);
                    __nv_bfloat16 l0 = __float2bfloat16(f0 - __bfloat162float(h0));
                    __nv_bfloat16 l1 = __float2bfloat16(f1 - __bfloat162float(h1));
                    hv[q * 2 + e] = (uint32_t)__bfloat16_as_ushort(h0) |
                                    ((uint32_t)__bfloat16_as_ushort(h1) << 16);
                    lv[q * 2 + e] = (uint32_t)__bfloat16_as_ushort(l0) |
                                    ((uint32_t)__bfloat16_as_ushort(l1) << 16);
                }
            }
            char* ab = sm + SM_A0 + stage * A_STAGE + sts_off;
            *(uint4*)(ab +  0) = make_uint4(hv[0], hv[1], hv[2], hv[3]);
            *(uint4*)(ab + 16) = make_uint4(hv[4], hv[5], hv[6], hv[7]);
            *(uint4*)(ab + SM_AL_OFF +  0) = make_uint4(lv[0], lv[1], lv[2], lv[3]);
            *(uint4*)(ab + SM_AL_OFF + 16) = make_uint4(lv[4], lv[5], lv[6], lv[7]);
        }
        __syncthreads();

        // prefetch next chunk (overlaps with compute below)
        if (c < 7 && grow < M) {
#pragma unroll
            for (int q = 0; q < 4; q++)
                pf[q] = *(const float4*)(aptr + (c + 1) * 32 + q * 4);
        }

        const uint32_t aB = sbase + SM_A0 + stage * A_STAGE + a_frag_off;
        const uint32_t bB = sbase + b_frag_off + c * 64;    // k0 bytes = c*32*2
#pragma unroll
        for (int ks = 0; ks < 2; ks++) {
            uint32_t ahf[2][4], alf[2][4];
#pragma unroll
            for (int mf = 0; mf < 2; mf++) {
                ldsm_x4(ahf[mf], aB + mf * (16 * A_ROW) + ks * 32);
                ldsm_x4(alf[mf], aB + SM_AL_OFF + mf * (16 * A_ROW) + ks * 32);
            }
            uint32_t bhf[4][2], blf[4][2];
#pragma unroll
            for (int nf = 0; nf < 4; nf++) {
                ldsm_x2(bhf[nf], bB + SM_BH + nf * (8 * B_ROW) + ks * 32);
                ldsm_x2(blf[nf], bB + SM_BL + nf * (8 * B_ROW) + ks * 32);
            }
#pragma unroll
            for (int mf = 0; mf < 2; mf++)
#pragma unroll
                for (int nf = 0; nf < 4; nf++) {
                    mma_bf16(acc[mf][nf], ahf[mf], bhf[nf]);
                    mma_bf16(acc[mf][nf], ahf[mf], blf[nf]);
                    mma_bf16(acc[mf][nf], alf[mf], bhf[nf]);
                }
        }
        __syncthreads();
    }

    // epilogue -> fp16
#pragma unroll
    for (int mf = 0; mf < 2; mf++) {
        int r0 = rowBase + wm * 32 + mf * 16 + (lane >> 2);
#pragma unroll
        for (int nf = 0; nf < 4; nf++) {
            int col = colBase + wn * 32 + nf * 8 + 2 * (lane & 3);
            if (r0 < M)
                *(__half2*)(g_Wh_h + (size_t)r0 * OUT_F + col) =
                    __floats2half2_rn(acc[mf][nf][0], acc[mf][nf][1]);
            if (r0 + 8 < M)
                *(__half2*)(g_Wh_h + (size_t)(r0 + 8) * OUT_F + col) =
                    __floats2half2_rn(acc[mf][nf][2], acc[mf][nf][3]);
        }
    }
}

// ---------------------------------------------------------------------------
// Kernel 2: degree histogram over src   (adj is INT32: [2, E] row-major)
// ---------------------------------------------------------------------------
__global__ void k_count(const int* __restrict__ adj, int E) {
    int e = blockIdx.x * blockDim.x + threadIdx.x;
    if (e < E) atomicAdd(&g_deg[adj[e]], 1);
}

// ---------------------------------------------------------------------------
// Kernels 3-5: exclusive scan of g_deg -> g_rowstart (and g_cursor copy)
// ---------------------------------------------------------------------------
__global__ void k_scan1(int n) {
    __shared__ int sm[SCAN_BLK];
    int i = blockIdx.x * SCAN_BLK + threadIdx.x;
    int v = (i < n) ? g_deg[i] : 0;
    sm[threadIdx.x] = v;
    __syncthreads();
    for (int off = 1; off < SCAN_BLK; off <<= 1) {
        int add = (threadIdx.x >= off) ? sm[threadIdx.x - off] : 0;
        __syncthreads();
        sm[threadIdx.x] += add;
        __syncthreads();
    }
    if (i < n) g_rowstart[i] = sm[threadIdx.x] - v;
    if (threadIdx.x == SCAN_BLK - 1) g_bsum[blockIdx.x] = sm[SCAN_BLK - 1];
}

__global__ void k_scan2(int nb) {
    __shared__ int sm[256];
    int t = threadIdx.x;
    int v = (t < nb) ? g_bsum[t] : 0;
    sm[t] = v;
    __syncthreads();
    for (int off = 1; off < 256; off <<= 1) {
        int add = (t >= off) ? sm[t - off] : 0;
        __syncthreads();
        sm[t] += add;
        __syncthreads();
    }
    if (t < nb) g_bsum[t] = sm[t] - v;
}

__global__ void k_scan3(int n) {
    int i = blockIdx.x * blockDim.x + threadIdx.x;
    if (i < n) {
        int rs = g_rowstart[i] + g_bsum[i >> 9];
        g_rowstart[i] = rs;
        g_cursor[i]   = rs;
    }
}

// ---------------------------------------------------------------------------
// Kernel 6: scatter edges into CSR (dst per slot)
// ---------------------------------------------------------------------------
__global__ void k_scatter(const int* __restrict__ adj, int E) {
    int e = blockIdx.x * blockDim.x + threadIdx.x;
    if (e < E) {
        int s = adj[e];
        int d = adj[E + e];
        int p = atomicAdd(&g_cursor[s], 1);
        g_edst[p] = d;
    }
}

// ---------------------------------------------------------------------------
// Kernel 7a: warp-per-node attention -> normalized weights in g_att
// ---------------------------------------------------------------------------
__global__ __launch_bounds__(256) void k_attention(
    const float* __restrict__ label,   // [N, 32]
    int n)
{
    const int wl   = threadIdx.x >> 5;
    const int lane = threadIdx.x & 31;
    const int w    = blockIdx.x * 8 + wl;
    if (w >= n) return;

    const float labi = label[(size_t)w * D_LABEL + lane];
    const int start = g_rowstart[w];
    const int d     = g_deg[w];

    float denom = 0.0f;
    int k = 0;
    for (; k + 1 < d; k += 2) {
        int j0 = __ldg(g_edst + start + k);
        int j1 = __ldg(g_edst + start + k + 1);
        float v0 = labi * __ldg(label + (size_t)j0 * D_LABEL + lane);
        float v1 = labi * __ldg(label + (size_t)j1 * D_LABEL + lane);
#pragma unroll
        for (int o = 16; o > 0; o >>= 1) {
            v0 += __shfl_xor_sync(0xffffffffu, v0, o);
            v1 += __shfl_xor_sync(0xffffffffu, v1, o);
        }
        float e0 = (v0 >= 0.0f) ? v0 : ALPHA * v0;
        float e1 = (v1 >= 0.0f) ? v1 : ALPHA * v1;
        float ex0 = __expf(e0);
        float ex1 = __expf(e1);
        denom += ex0 + ex1;
        if (lane == (k & 31))       g_att[start + k]     = ex0;
        if (lane == ((k + 1) & 31)) g_att[start + k + 1] = ex1;
    }
    if (k < d) {
        int j0 = __ldg(g_edst + start + k);
        float v0 = labi * __ldg(label + (size_t)j0 * D_LABEL + lane);
#pragma unroll
        for (int o = 16; o > 0; o >>= 1)
            v0 += __shfl_xor_sync(0xffffffffu, v0, o);
        float e0 = (v0 >= 0.0f) ? v0 : ALPHA * v0;
        float ex0 = __expf(e0);
        denom += ex0;
        if (lane == (k & 31)) g_att[start + k] = ex0;
    }
    const float inv = 1.0f / fmaxf(denom, EPS_RS);
    for (int t = lane; t < d; t += 32)
        g_att[start + t] *= inv;
}

// ---------------------------------------------------------------------------
// Kernel 7b: gather — 1 warp per node; lane covers 8 cols (uint4 of fp16);
// 4 edges in flight; streaming (__stcs) output stores to protect Wh in L2
// ---------------------------------------------------------------------------
__device__ __forceinline__ void fma8_h(float* acc, uint4 v, float a) {
    float2 f;
    f = __half22float2(*(__half2*)&v.x);
    acc[0] = fmaf(a, f.x, acc[0]); acc[1] = fmaf(a, f.y, acc[1]);
    f = __half22float2(*((__half2*)&v.x + 1));
    acc[2] = fmaf(a, f.x, acc[2]); acc[3] = fmaf(a, f.y, acc[3]);
    f = __half22float2(*(__half2*)&v.z);
    acc[4] = fmaf(a, f.x, acc[4]); acc[5] = fmaf(a, f.y, acc[5]);
    f = __half22float2(*((__half2*)&v.z + 1));
    acc[6] = fmaf(a, f.x, acc[6]); acc[7] = fmaf(a, f.y, acc[7]);
}

__global__ __launch_bounds__(256) void k_gather(
    float* __restrict__ out,   // [N, 256]
    int n)
{
    const int w    = blockIdx.x * 8 + (threadIdx.x >> 5);
    const int lane = threadIdx.x & 31;
    if (w >= n) return;

    const int start = g_rowstart[w];
    const int d     = g_deg[w];
    const __half* base = g_Wh_h + lane * 8;   // 16B per lane, 512B per warp row

    float acc[8];
#pragma unroll
    for (int q = 0; q < 8; q++) acc[q] = 0.0f;

    int k = 0;
    for (; k + 3 < d; k += 4) {
        int j0 = __ldg(g_edst + start + k);
        int j1 = __ldg(g_edst + start + k + 1);
        int j2 = __ldg(g_edst + start + k + 2);
        int j3 = __ldg(g_edst + start + k + 3);
        float a0 = __ldg(g_att + start + k);
        float a1 = __ldg(g_att + start + k + 1);
        float a2 = __ldg(g_att + start + k + 2);
        float a3 = __ldg(g_att + start + k + 3);
        uint4 v0 = __ldg((const uint4*)(base + (size_t)j0 * OUT_F));
        uint4 v1 = __ldg((const uint4*)(base + (size_t)j1 * OUT_F));
        uint4 v2 = __ldg((const uint4*)(base + (size_t)j2 * OUT_F));
        uint4 v3 = __ldg((const uint4*)(base + (size_t)j3 * OUT_F));
        fma8_h(acc, v0, a0);
        fma8_h(acc, v1, a1);
        fma8_h(acc, v2, a2);
        fma8_h(acc, v3, a3);
    }
    for (; k < d; k++) {
        int j0 = __ldg(g_edst + start + k);
        float a0 = __ldg(g_att + start + k);
        uint4 v0 = __ldg((const uint4*)(base + (size_t)j0 * OUT_F));
        fma8_h(acc, v0, a0);
    }

    float* o = out + (size_t)w * OUT_F + lane * 8;
    __stcs((float4*)(o + 0), make_float4(acc[0], acc[1], acc[2], acc[3]));
    __stcs((float4*)(o + 4), make_float4(acc[4], acc[5], acc[6], acc[7]));
}

// ---------------------------------------------------------------------------
// Launch — stream fork: branch A = prep_W + GEMM (default stream),
//                        branch B = CSR build + attention (s2), join -> gather
// ---------------------------------------------------------------------------
extern "C" void kernel_launch(void* const* d_in, const int* in_sizes, int n_in,
                              void* d_out, int out_size)
{
    const float* h     = (const float*)d_in[0];   // [N, 256] fp32
    const float* label = (const float*)d_in[1];   // [N, 32]  fp32
    const float* W     = (const float*)d_in[2];   // [256, 256] fp32
    const int*   adj   = (const int*)d_in[3];     // [2, E] int32
    float*       out   = (float*)d_out;

    const int N = in_sizes[0] / IN_F;      // 100000
    const int E = in_sizes[3] / 2;         // 1600000

    const int T = 256;
    const int gbN = (N + T - 1) / T;
    const int gbE = (E + T - 1) / T;

    static cudaStream_t s2 = nullptr;
    static cudaEvent_t  evF = nullptr, evJ = nullptr;
    if (s2 == nullptr) {
        cudaFuncSetAttribute(k_gemm_mma, cudaFuncAttributeMaxDynamicSharedMemorySize, GSM_TOTAL);
        cudaStreamCreateWithFlags(&s2, cudaStreamNonBlocking);
        cudaEventCreateWithFlags(&evF, cudaEventDisableTiming);
        cudaEventCreateWithFlags(&evJ, cudaEventDisableTiming);
    }

    // fork
    cudaEventRecord(evF, 0);
    cudaStreamWaitEvent(s2, evF, 0);

    // ---- branch B (s2): CSR build + attention weights
    k_zero_deg<<<gbN, T, 0, s2>>>(N);
    k_count<<<gbE, T, 0, s2>>>(adj, E);
    int nb = (N + SCAN_BLK - 1) / SCAN_BLK;
    k_scan1<<<nb, SCAN_BLK, 0, s2>>>(N);
    k_scan2<<<1, 256, 0, s2>>>(nb);
    k_scan3<<<gbN, T, 0, s2>>>(N);
    k_scatter<<<gbE, T, 0, s2>>>(adj, E);
    k_attention<<<(N + 7) / 8, 256, 0, s2>>>(label, N);
    cudaEventRecord(evJ, s2);

    // ---- branch A (default stream): GEMM
    k_prep_W<<<256, 256>>>(W);
    dim3 ggrid(4, (N + 127) / 128);     // 4 N-quarters of 64 cols
    k_gemm_mma<<<ggrid, 256, GSM_TOTAL>>>(h, N);

    // join, then gather
    cudaStreamWaitEvent(0, evJ, 0);
    k_gather<<<(N + 7) / 8, 256>>>(out, N);
}

// round 9
// speedup vs baseline: 1.0209x; 1.0209x over previous
#include <cuda_runtime.h>
#include <cuda_bf16.h>
#include <cuda_fp16.h>
#include <math.h>
#include <stdint.h>

// Problem constants (fixed by the dataset)
#define N_NODES   100000
#define N_EDGES   1600000
#define IN_F      256
#define OUT_F     256
#define D_LABEL   32
#define ALPHA     0.2f
#define EPS_RS    1e-9f

#define SCAN_BLK  512

// Scratch (device globals: allowed; no cudaMalloc anywhere)
__device__ __half g_Wh_h[(size_t)N_NODES * OUT_F];   // ~50 MB (fp16 Wh)
__device__ float g_att[N_EDGES];
__device__ int   g_deg[N_NODES];
__device__ int   g_rowstart[N_NODES];
__device__ int   g_cursor[N_NODES];
__device__ int   g_edst[N_EDGES];
__device__ int   g_bsum[256];
// W transposed + bf16 split: Wt[n][k] = W[k][n]
__device__ __nv_bfloat16 g_Wt_hi[256 * 256];
__device__ __nv_bfloat16 g_Wt_lo[256 * 256];

// ---------------------------------------------------------------------------
// helpers
// ---------------------------------------------------------------------------
__device__ __forceinline__ uint32_t smem_u32(const void* p) {
    uint32_t a;
    asm("{ .reg .u64 t; cvta.to.shared.u64 t, %1; cvt.u32.u64 %0, t; }"
        : "=r"(a) : "l"(p));
    return a;
}

__device__ __forceinline__ void ldsm_x4(uint32_t* r, uint32_t addr) {
    asm volatile("ldmatrix.sync.aligned.m8n8.x4.shared.b16 {%0,%1,%2,%3}, [%4];"
                 : "=r"(r[0]), "=r"(r[1]), "=r"(r[2]), "=r"(r[3]) : "r"(addr));
}
__device__ __forceinline__ void ldsm_x2(uint32_t* r, uint32_t addr) {
    asm volatile("ldmatrix.sync.aligned.m8n8.x2.shared.b16 {%0,%1}, [%2];"
                 : "=r"(r[0]), "=r"(r[1]) : "r"(addr));
}
__device__ __forceinline__ void mma_bf16(float* c, const uint32_t* a, const uint32_t* b) {
    asm volatile(
        "mma.sync.aligned.m16n8k16.row.col.f32.bf16.bf16.f32 "
        "{%0,%1,%2,%3}, {%4,%5,%6,%7}, {%8,%9}, {%0,%1,%2,%3};"
        : "+f"(c[0]), "+f"(c[1]), "+f"(c[2]), "+f"(c[3])
        : "r"(a[0]), "r"(a[1]), "r"(a[2]), "r"(a[3]), "r"(b[0]), "r"(b[1]));
}

// ---------------------------------------------------------------------------
// Kernel 0: zero degree array
// ---------------------------------------------------------------------------
__global__ void k_zero_deg(int n) {
    int i = blockIdx.x * blockDim.x + threadIdx.x;
    if (i < n) g_deg[i] = 0;
}

// ---------------------------------------------------------------------------
// Kernel P: W [K,N] fp32 -> Wt_hi/Wt_lo [N,K] bf16 split
// ---------------------------------------------------------------------------
__global__ void k_prep_W(const float* __restrict__ W) {
    int i = blockIdx.x * 256 + threadIdx.x;     // 0..65535
    int n = i >> 8, k = i & 255;
    float w = W[k * 256 + n];
    __nv_bfloat16 hi = __float2bfloat16(w);
    __nv_bfloat16 lo = __float2bfloat16(w - __bfloat162float(hi));
    g_Wt_hi[n * 256 + k] = hi;
    g_Wt_lo[n * 256 + k] = lo;
}

// ---------------------------------------------------------------------------
// Kernel 1: HMMA GEMM  Wh = h @ W  via bf16 hi/lo split (3 products)
// R7 config restored (measured 168.5us): CTA 128M x 128N, grid(2, M/128),
// B full-K resident, A reg-prefetch + double-buffered stages, fp16 epilogue.
// ---------------------------------------------------------------------------
#define B_ROW 528
#define A_ROW 80
#define SM_BH 0
#define SM_BL 67584
#define SM_A0 135168
#define A_STAGE 20480
#define SM_AL_OFF 10240
#define GSM_TOTAL 176128

__global__ __launch_bounds__(256, 1) void k_gemm_mma(const float* __restrict__ A, int M)
{
    extern __shared__ __align__(16) char sm[];
    const uint32_t sbase = smem_u32(sm);
    const int tid  = threadIdx.x;
    const int lane = tid & 31;
    const int wid  = tid >> 5;
    const int wm   = wid >> 2;          // 0..1
    const int wn   = wid & 3;           // 0..3
    const int rowBase = blockIdx.y * 128;
    const int colBase = blockIdx.x * 128;

    // ---- stage B (hi+lo, full K) into smem
    {
        const char* srcH = (const char*)(g_Wt_hi + (size_t)colBase * 256);
        const char* srcL = (const char*)(g_Wt_lo + (size_t)colBase * 256);
        for (int i = tid; i < 128 * 32; i += 256) {
            int n = i >> 5, c = i & 31;
            *(uint4*)(sm + SM_BH + n * B_ROW + c * 16) =
                *(const uint4*)(srcH + n * 512 + c * 16);
            *(uint4*)(sm + SM_BL + n * B_ROW + c * 16) =
                *(const uint4*)(srcL + n * 512 + c * 16);
        }
    }

    float acc[4][4][4];
#pragma unroll
    for (int i = 0; i < 4; i++)
#pragma unroll
        for (int j = 0; j < 4; j++)
#pragma unroll
            for (int q = 0; q < 4; q++) acc[i][j][q] = 0.0f;

    const int ar   = tid >> 1;
    const int ahlf = tid & 1;
    const int grow = rowBase + ar;
    const float* aptr = A + (size_t)grow * IN_F + ahlf * 16;

    float4 pf[4];
#pragma unroll
    for (int q = 0; q < 4; q++) pf[q] = make_float4(0.f, 0.f, 0.f, 0.f);
    if (grow < M) {
#pragma unroll
        for (int q = 0; q < 4; q++) pf[q] = *(const float4*)(aptr + q * 4);
    }

    const uint32_t a_frag_off = (uint32_t)((wm * 64 + (lane & 15)) * A_ROW + (lane >> 4) * 16);
    const int bl_ = lane & 15;
    const uint32_t b_frag_off = (uint32_t)((wn * 32 + (bl_ & 7)) * B_ROW + ((bl_ >> 3) & 1) * 16);
    const uint32_t sts_off = (uint32_t)(ar * A_ROW + ahlf * 32);

    for (int c = 0; c < 8; c++) {
        const int stage = c & 1;
        {
            uint32_t hv[8], lv[8];
#pragma unroll
            for (int q = 0; q < 4; q++) {
                float x[4] = { pf[q].x, pf[q].y, pf[q].z, pf[q].w };
#pragma unroll
                for (int e = 0; e < 2; e++) {
                    float f0 = x[e * 2], f1 = x[e * 2 + 1];
                    __nv_bfloat16 h0 = __float2bfloat16(f0);
                    __nv_bfloat16 h1 = __float2bfloat16(f1);
                    __nv_bfloat16 l0 = __float2bfloat16(f0 - __bfloat162float(h0));
                    __nv_bfloat16 l1 = __float2bfloat16(f1 - __bfloat162float(h1));
                    hv[q * 2 + e] = (uint32_t)__bfloat16_as_ushort(h0) |
                                    ((uint32_t)__bfloat16_as_ushort(h1) << 16);
                    lv[q * 2 + e] = (uint32_t)__bfloat16_as_ushort(l0) |
                                    ((uint32_t)__bfloat16_as_ushort(l1) << 16);
                }
            }
            char* ab = sm + SM_A0 + stage * A_STAGE + sts_off;
            *(uint4*)(ab +  0) = make_uint4(hv[0], hv[1], hv[2], hv[3]);
            *(uint4*)(ab + 16) = make_uint4(hv[4], hv[5], hv[6], hv[7]);
            *(uint4*)(ab + SM_AL_OFF +  0) = make_uint4(lv[0], lv[1], lv[2], lv[3]);
            *(uint4*)(ab + SM_AL_OFF + 16) = make_uint4(lv[4], lv[5], lv[6], lv[7]);
        }
        __syncthreads();

        if (c < 7 && grow < M) {
#pragma unroll
            for (int q = 0; q < 4; q++)
                pf[q] = *(const float4*)(aptr + (c + 1) * 32 + q * 4);
        }

        const uint32_t aB = sbase + SM_A0 + stage * A_STAGE + a_frag_off;
        const uint32_t bB = sbase + b_frag_off + c * 64;
#pragma unroll
        for (int ks = 0; ks < 2; ks++) {
            uint32_t ahf[4][4], alf[4][4];
#pragma unroll
            for (int mf = 0; mf < 4; mf++) {
                ldsm_x4(ahf[mf], aB + mf * (16 * A_ROW) + ks * 32);
                ldsm_x4(alf[mf], aB + SM_AL_OFF + mf * (16 * A_ROW) + ks * 32);
            }
            uint32_t bhf[4][2], blf[4][2];
#pragma unroll
            for (int nf = 0; nf < 4; nf++) {
                ldsm_x2(bhf[nf], bB + SM_BH + nf * (8 * B_ROW) + ks * 32);
                ldsm_x2(blf[nf], bB + SM_BL + nf * (8 * B_ROW) + ks * 32);
            }
#pragma unroll
            for (int mf = 0; mf < 4; mf++)
#pragma unroll
                for (int nf = 0; nf < 4; nf++) {
                    mma_bf16(acc[mf][nf], ahf[mf], bhf[nf]);
                    mma_bf16(acc[mf][nf], ahf[mf], blf[nf]);
                    mma_bf16(acc[mf][nf], alf[mf], bhf[nf]);
                }
        }
    }

    // epilogue -> fp16
#pragma unroll
    for (int mf = 0; mf < 4; mf++) {
        int r0 = rowBase + wm * 64 + mf * 16 + (lane >> 2);
#pragma unroll
        for (int nf = 0; nf < 4; nf++) {
            int col = colBase + wn * 32 + nf * 8 + 2 * (lane & 3);
            if (r0 < M)
                *(__half2*)(g_Wh_h + (size_t)r0 * OUT_F + col) =
                    __floats2half2_rn(acc[mf][nf][0], acc[mf][nf][1]);
            if (r0 + 8 < M)
                *(__half2*)(g_Wh_h + (size_t)(r0 + 8) * OUT_F + col) =
                    __floats2half2_rn(acc[mf][nf][2], acc[mf][nf][3]);
        }
    }
}

// ---------------------------------------------------------------------------
// Kernel 2: degree histogram over src   (adj is INT32: [2, E] row-major)
// ---------------------------------------------------------------------------
__global__ void k_count(const int* __restrict__ adj, int E) {
    int e = blockIdx.x * blockDim.x + threadIdx.x;
    if (e < E) atomicAdd(&g_deg[adj[e]], 1);
}

// ---------------------------------------------------------------------------
// Kernels 3-5: exclusive scan of g_deg -> g_rowstart (and g_cursor copy)
// ---------------------------------------------------------------------------
__global__ void k_scan1(int n) {
    __shared__ int sm[SCAN_BLK];
    int i = blockIdx.x * SCAN_BLK + threadIdx.x;
    int v = (i < n) ? g_deg[i] : 0;
    sm[threadIdx.x] = v;
    __syncthreads();
    for (int off = 1; off < SCAN_BLK; off <<= 1) {
        int add = (threadIdx.x >= off) ? sm[threadIdx.x - off] : 0;
        __syncthreads();
        sm[threadIdx.x] += add;
        __syncthreads();
    }
    if (i < n) g_rowstart[i] = sm[threadIdx.x] - v;
    if (threadIdx.x == SCAN_BLK - 1) g_bsum[blockIdx.x] = sm[SCAN_BLK - 1];
}

__global__ void k_scan2(int nb) {
    __shared__ int sm[256];
    int t = threadIdx.x;
    int v = (t < nb) ? g_bsum[t] : 0;
    sm[t] = v;
    __syncthreads();
    for (int off = 1; off < 256; off <<= 1) {
        int add = (t >= off) ? sm[t - off] : 0;
        __syncthreads();
        sm[t] += add;
        __syncthreads();
    }
    if (t < nb) g_bsum[t] = sm[t] - v;
}

__global__ void k_scan3(int n) {
    int i = blockIdx.x * blockDim.x + threadIdx.x;
    if (i < n) {
        int rs = g_rowstart[i] + g_bsum[i >> 9];
        g_rowstart[i] = rs;
        g_cursor[i]   = rs;
    }
}

// ---------------------------------------------------------------------------
// Kernel 6: scatter edges into CSR (dst per slot)
// ---------------------------------------------------------------------------
__global__ void k_scatter(const int* __restrict__ adj, int E) {
    int e = blockIdx.x * blockDim.x + threadIdx.x;
    if (e < E) {
        int s = adj[e];
        int d = adj[E + e];
        int p = atomicAdd(&g_cursor[s], 1);
        g_edst[p] = d;
    }
}

// ---------------------------------------------------------------------------
// Kernel 7a: warp-per-node attention -> normalized weights in g_att
// ---------------------------------------------------------------------------
__global__ __launch_bounds__(256) void k_attention(
    const float* __restrict__ label,   // [N, 32]
    int n)
{
    const int wl   = threadIdx.x >> 5;
    const int lane = threadIdx.x & 31;
    const int w    = blockIdx.x * 8 + wl;
    if (w >= n) return;

    const float labi = label[(size_t)w * D_LABEL + lane];
    const int start = g_rowstart[w];
    const int d     = g_deg[w];

    float denom = 0.0f;
    int k = 0;
    for (; k + 1 < d; k += 2) {
        int j0 = __ldg(g_edst + start + k);
        int j1 = __ldg(g_edst + start + k + 1);
        float v0 = labi * __ldg(label + (size_t)j0 * D_LABEL + lane);
        float v1 = labi * __ldg(label + (size_t)j1 * D_LABEL + lane);
#pragma unroll
        for (int o = 16; o > 0; o >>= 1) {
            v0 += __shfl_xor_sync(0xffffffffu, v0, o);
            v1 += __shfl_xor_sync(0xffffffffu, v1, o);
        }
        float e0 = (v0 >= 0.0f) ? v0 : ALPHA * v0;
        float e1 = (v1 >= 0.0f) ? v1 : ALPHA * v1;
        float ex0 = __expf(e0);
        float ex1 = __expf(e1);
        denom += ex0 + ex1;
        if (lane == (k & 31))       g_att[start + k]     = ex0;
        if (lane == ((k + 1) & 31)) g_att[start + k + 1] = ex1;
    }
    if (k < d) {
        int j0 = __ldg(g_edst + start + k);
        float v0 = labi * __ldg(label + (size_t)j0 * D_LABEL + lane);
#pragma unroll
        for (int o = 16; o > 0; o >>= 1)
            v0 += __shfl_xor_sync(0xffffffffu, v0, o);
        float e0 = (v0 >= 0.0f) ? v0 : ALPHA * v0;
        float ex0 = __expf(e0);
        denom += ex0;
        if (lane == (k & 31)) g_att[start + k] = ex0;
    }
    const float inv = 1.0f / fmaxf(denom, EPS_RS);
    for (int t = lane; t < d; t += 32)
        g_att[start + t] *= inv;
}

// ---------------------------------------------------------------------------
// Kernel 7b: gather — 1 warp per node; warp-batched edge metadata (coalesced
// loads + shfl broadcast), 4 row-loads in flight, __stcs output
// ---------------------------------------------------------------------------
__device__ __forceinline__ void fma8_h(float* acc, uint4 v, float a) {
    float2 f;
    f = __half22float2(*(__half2*)&v.x);
    acc[0] = fmaf(a, f.x, acc[0]); acc[1] = fmaf(a, f.y, acc[1]);
    f = __half22float2(*((__half2*)&v.x + 1));
    acc[2] = fmaf(a, f.x, acc[2]); acc[3] = fmaf(a, f.y, acc[3]);
    f = __half22float2(*(__half2*)&v.z);
    acc[4] = fmaf(a, f.x, acc[4]); acc[5] = fmaf(a, f.y, acc[5]);
    f = __half22float2(*((__half2*)&v.z + 1));
    acc[6] = fmaf(a, f.x, acc[6]); acc[7] = fmaf(a, f.y, acc[7]);
}

__global__ __launch_bounds__(256) void k_gather(
    float* __restrict__ out,   // [N, 256]
    int n)
{
    const int w    = blockIdx.x * 8 + (threadIdx.x >> 5);
    const int lane = threadIdx.x & 31;
    if (w >= n) return;

    const int start = g_rowstart[w];
    const int d     = g_deg[w];
    const __half* base = g_Wh_h + lane * 8;   // 16B per lane, 512B per warp row

    float acc[8];
#pragma unroll
    for (int q = 0; q < 8; q++) acc[q] = 0.0f;

    for (int c0 = 0; c0 < d; c0 += 32) {
        const int m = min(32, d - c0);
        // warp-batched metadata: one coalesced load each for up to 32 edges
        int   jv = 0;
        float av = 0.0f;
        if (lane < m) {
            jv = __ldg(g_edst + start + c0 + lane);
            av = __ldg(g_att  + start + c0 + lane);
        }

        int k = 0;
        for (; k + 3 < m; k += 4) {
            int   j0 = __shfl_sync(0xffffffffu, jv, k);
            int   j1 = __shfl_sync(0xffffffffu, jv, k + 1);
            int   j2 = __shfl_sync(0xffffffffu, jv, k + 2);
            int   j3 = __shfl_sync(0xffffffffu, jv, k + 3);
            float a0 = __shfl_sync(0xffffffffu, av, k);
            float a1 = __shfl_sync(0xffffffffu, av, k + 1);
            float a2 = __shfl_sync(0xffffffffu, av, k + 2);
            float a3 = __shfl_sync(0xffffffffu, av, k + 3);
            uint4 v0 = __ldg((const uint4*)(base + (size_t)j0 * OUT_F));
            uint4 v1 = __ldg((const uint4*)(base + (size_t)j1 * OUT_F));
            uint4 v2 = __ldg((const uint4*)(base + (size_t)j2 * OUT_F));
            uint4 v3 = __ldg((const uint4*)(base + (size_t)j3 * OUT_F));
            fma8_h(acc, v0, a0);
            fma8_h(acc, v1, a1);
            fma8_h(acc, v2, a2);
            fma8_h(acc, v3, a3);
        }
        for (; k < m; k++) {
            int   j0 = __shfl_sync(0xffffffffu, jv, k);
            float a0 = __shfl_sync(0xffffffffu, av, k);
            uint4 v0 = __ldg((const uint4*)(base + (size_t)j0 * OUT_F));
            fma8_h(acc, v0, a0);
        }
    }

    float* o = out + (size_t)w * OUT_F + lane * 8;
    __stcs((float4*)(o + 0), make_float4(acc[0], acc[1], acc[2], acc[3]));
    __stcs((float4*)(o + 4), make_float4(acc[4], acc[5], acc[6], acc[7]));
}

// ---------------------------------------------------------------------------
// Launch — stream fork: branch A = prep_W + GEMM (default stream),
//                        branch B = CSR build + attention (s2), join -> gather
// ---------------------------------------------------------------------------
extern "C" void kernel_launch(void* const* d_in, const int* in_sizes, int n_in,
                              void* d_out, int out_size)
{
    const float* h     = (const float*)d_in[0];   // [N, 256] fp32
    const float* label = (const float*)d_in[1];   // [N, 32]  fp32
    const float* W     = (const float*)d_in[2];   // [256, 256] fp32
    const int*   adj   = (const int*)d_in[3];     // [2, E] int32
    float*       out   = (float*)d_out;

    const int N = in_sizes[0] / IN_F;      // 100000
    const int E = in_sizes[3] / 2;         // 1600000

    const int T = 256;
    const int gbN = (N + T - 1) / T;
    const int gbE = (E + T - 1) / T;

    static cudaStream_t s2 = nullptr;
    static cudaEvent_t  evF = nullptr, evJ = nullptr;
    if (s2 == nullptr) {
        cudaFuncSetAttribute(k_gemm_mma, cudaFuncAttributeMaxDynamicSharedMemorySize, GSM_TOTAL);
        cudaStreamCreateWithFlags(&s2, cudaStreamNonBlocking);
        cudaEventCreateWithFlags(&evF, cudaEventDisableTiming);
        cudaEventCreateWithFlags(&evJ, cudaEventDisableTiming);
    }

    // fork
    cudaEventRecord(evF, 0);
    cudaStreamWaitEvent(s2, evF, 0);

    // ---- branch B (s2): CSR build + attention weights
    k_zero_deg<<<gbN, T, 0, s2>>>(N);
    k_count<<<gbE, T, 0, s2>>>(adj, E);
    int nb = (N + SCAN_BLK - 1) / SCAN_BLK;
    k_scan1<<<nb, SCAN_BLK, 0, s2>>>(N);
    k_scan2<<<1, 256, 0, s2>>>(nb);
    k_scan3<<<gbN, T, 0, s2>>>(N);
    k_scatter<<<gbE, T, 0, s2>>>(adj, E);
    k_attention<<<(N + 7) / 8, 256, 0, s2>>>(label, N);
    cudaEventRecord(evJ, s2);

    // ---- branch A (default stream): GEMM (R7 config: grid.x = 2)
    k_prep_W<<<256, 256>>>(W);
    dim3 ggrid(2, (N + 127) / 128);
    k_gemm_mma<<<ggrid, 256, GSM_TOTAL>>>(h, N);

    // join, then gather
    cudaStreamWaitEvent(0, evJ, 0);
    k_gather<<<(N + 7) / 8, 256>>>(out, N);
}

// round 10
// speedup vs baseline: 1.0665x; 1.0446x over previous
#include <cuda_runtime.h>
#include <cuda_bf16.h>
#include <cuda_fp16.h>
#include <math.h>
#include <stdint.h>

// Problem constants (fixed by the dataset)
#define N_NODES   100000
#define N_EDGES   1600000
#define IN_F      256
#define OUT_F     256
#define D_LABEL   32
#define ALPHA     0.2f
#define EPS_RS    1e-9f

#define SCAN_BLK  512

// Scratch (device globals: allowed; no cudaMalloc anywhere)
__device__ __half g_Wh_h[(size_t)N_NODES * OUT_F];   // ~50 MB (fp16 Wh)
__device__ float g_att[N_EDGES];
__device__ int   g_deg[N_NODES];
__device__ int   g_rowstart[N_NODES];
__device__ int   g_cursor[N_NODES];
__device__ int   g_edst[N_EDGES];
__device__ int   g_bsum[256];
// W transposed + bf16 split: Wt[n][k] = W[k][n]
__device__ __nv_bfloat16 g_Wt_hi[256 * 256];
__device__ __nv_bfloat16 g_Wt_lo[256 * 256];

// ---------------------------------------------------------------------------
// helpers
// ---------------------------------------------------------------------------
__device__ __forceinline__ uint32_t smem_u32(const void* p) {
    uint32_t a;
    asm("{ .reg .u64 t; cvta.to.shared.u64 t, %1; cvt.u32.u64 %0, t; }"
        : "=r"(a) : "l"(p));
    return a;
}

__device__ __forceinline__ void ldsm_x4(uint32_t* r, uint32_t addr) {
    asm volatile("ldmatrix.sync.aligned.m8n8.x4.shared.b16 {%0,%1,%2,%3}, [%4];"
                 : "=r"(r[0]), "=r"(r[1]), "=r"(r[2]), "=r"(r[3]) : "r"(addr));
}
__device__ __forceinline__ void mma_bf16(float* c, const uint32_t* a, const uint32_t* b) {
    asm volatile(
        "mma.sync.aligned.m16n8k16.row.col.f32.bf16.bf16.f32 "
        "{%0,%1,%2,%3}, {%4,%5,%6,%7}, {%8,%9}, {%0,%1,%2,%3};"
        : "+f"(c[0]), "+f"(c[1]), "+f"(c[2]), "+f"(c[3])
        : "r"(a[0]), "r"(a[1]), "r"(a[2]), "r"(a[3]), "r"(b[0]), "r"(b[1]));
}

// ---------------------------------------------------------------------------
// Kernel 0: zero degree array
// ---------------------------------------------------------------------------
__global__ void k_zero_deg(int n) {
    int i = blockIdx.x * blockDim.x + threadIdx.x;
    if (i < n) g_deg[i] = 0;
}

// ---------------------------------------------------------------------------
// Kernel P: W [K,N] fp32 -> Wt_hi/Wt_lo [N,K] bf16 split
// ---------------------------------------------------------------------------
__global__ void k_prep_W(const float* __restrict__ W) {
    int i = blockIdx.x * 256 + threadIdx.x;     // 0..65535
    int n = i >> 8, k = i & 255;
    float w = W[k * 256 + n];
    __nv_bfloat16 hi = __float2bfloat16(w);
    __nv_bfloat16 lo = __float2bfloat16(w - __bfloat162float(hi));
    g_Wt_hi[n * 256 + k] = hi;
    g_Wt_lo[n * 256 + k] = lo;
}

// ---------------------------------------------------------------------------
// Kernel 1: HMMA GEMM  Wh = h @ W  via bf16 hi/lo split (3 products)
// R7 tile config (128M x 128N, grid(2, M/128)); R10 change: B fragments via
// ldmatrix.x4 covering nf pairs -> LDSM ops per ks drop 16 -> 12.
// ---------------------------------------------------------------------------
#define B_ROW 528
#define A_ROW 80
#define SM_BH 0
#define SM_BL 67584
#define SM_A0 135168
#define A_STAGE 20480
#define SM_AL_OFF 10240
#define GSM_TOTAL 176128

__global__ __launch_bounds__(256, 1) void k_gemm_mma(const float* __restrict__ A, int M)
{
    extern __shared__ __align__(16) char sm[];
    const uint32_t sbase = smem_u32(sm);
    const int tid  = threadIdx.x;
    const int lane = tid & 31;
    const int wid  = tid >> 5;
    const int wm   = wid >> 2;          // 0..1
    const int wn   = wid & 3;           // 0..3
    const int rowBase = blockIdx.y * 128;
    const int colBase = blockIdx.x * 128;

    // ---- stage B (hi+lo, full K) into smem
    {
        const char* srcH = (const char*)(g_Wt_hi + (size_t)colBase * 256);
        const char* srcL = (const char*)(g_Wt_lo + (size_t)colBase * 256);
        for (int i = tid; i < 128 * 32; i += 256) {
            int n = i >> 5, c = i & 31;
            *(uint4*)(sm + SM_BH + n * B_ROW + c * 16) =
                *(const uint4*)(srcH + n * 512 + c * 16);
            *(uint4*)(sm + SM_BL + n * B_ROW + c * 16) =
                *(const uint4*)(srcL + n * 512 + c * 16);
        }
    }

    float acc[4][4][4];
#pragma unroll
    for (int i = 0; i < 4; i++)
#pragma unroll
        for (int j = 0; j < 4; j++)
#pragma unroll
            for (int q = 0; q < 4; q++) acc[i][j][q] = 0.0f;

    const int ar   = tid >> 1;
    const int ahlf = tid & 1;
    const int grow = rowBase + ar;
    const float* aptr = A + (size_t)grow * IN_F + ahlf * 16;

    float4 pf[4];
#pragma unroll
    for (int q = 0; q < 4; q++) pf[q] = make_float4(0.f, 0.f, 0.f, 0.f);
    if (grow < M) {
#pragma unroll
        for (int q = 0; q < 4; q++) pf[q] = *(const float4*)(aptr + q * 4);
    }

    const uint32_t a_frag_off = (uint32_t)((wm * 64 + (lane & 15)) * A_ROW + (lane >> 4) * 16);
    // B x4 fragment addressing: lanes 0-7 -> rows 0-7 (k-half 0), 8-15 -> rows 0-7
    // (k-half 1), 16-23 -> rows 8-15 (k-half 0), 24-31 -> rows 8-15 (k-half 1)
    const uint32_t b4_frag_off = (uint32_t)(
        (wn * 32 + (lane & 7) + ((lane >> 4) & 1) * 8) * B_ROW + ((lane >> 3) & 1) * 16);
    const uint32_t sts_off = (uint32_t)(ar * A_ROW + ahlf * 32);

    for (int c = 0; c < 8; c++) {
        const int stage = c & 1;
        {
            uint32_t hv[8], lv[8];
#pragma unroll
            for (int q = 0; q < 4; q++) {
                float x[4] = { pf[q].x, pf[q].y, pf[q].z, pf[q].w };
#pragma unroll
                for (int e = 0; e < 2; e++) {
                    float f0 = x[e * 2], f1 = x[e * 2 + 1];
                    __nv_bfloat16 h0 = __float2bfloat16(f0);
                    __nv_bfloat16 h1 = __float2bfloat16(f1);
                    __nv_bfloat16 l0 = __float2bfloat16(f0 - __bfloat162float(h0));
                    __nv_bfloat16 l1 = __float2bfloat16(f1 - __bfloat162float(h1));
                    hv[q * 2 + e] = (uint32_t)__bfloat16_as_ushort(h0) |
                                    ((uint32_t)__bfloat16_as_ushort(h1) << 16);
                    lv[q * 2 + e] = (uint32_t)__bfloat16_as_ushort(l0) |
                                    ((uint32_t)__bfloat16_as_ushort(l1) << 16);
                }
            }
            char* ab = sm + SM_A0 + stage * A_STAGE + sts_off;
            *(uint4*)(ab +  0) = make_uint4(hv[0], hv[1], hv[2], hv[3]);
            *(uint4*)(ab + 16) = make_uint4(hv[4], hv[5], hv[6], hv[7]);
            *(uint4*)(ab + SM_AL_OFF +  0) = make_uint4(lv[0], lv[1], lv[2], lv[3]);
            *(uint4*)(ab + SM_AL_OFF + 16) = make_uint4(lv[4], lv[5], lv[6], lv[7]);
        }
        __syncthreads();

        if (c < 7 && grow < M) {
#pragma unroll
            for (int q = 0; q < 4; q++)
                pf[q] = *(const float4*)(aptr + (c + 1) * 32 + q * 4);
        }

        const uint32_t aB = sbase + SM_A0 + stage * A_STAGE + a_frag_off;
        const uint32_t bB = sbase + b4_frag_off + c * 64;   // k0 bytes = c*32*2
#pragma unroll
        for (int ks = 0; ks < 2; ks++) {
            uint32_t ahf[4][4], alf[4][4];
#pragma unroll
            for (int mf = 0; mf < 4; mf++) {
                ldsm_x4(ahf[mf], aB + mf * (16 * A_ROW) + ks * 32);
                ldsm_x4(alf[mf], aB + SM_AL_OFF + mf * (16 * A_ROW) + ks * 32);
            }
            // B: 2 x4 loads per half cover nf = 0..3
            // bh4[p] = {nf=2p k0, nf=2p k1, nf=2p+1 k0, nf=2p+1 k1}
            uint32_t bh4[2][4], bl4[2][4];
#pragma unroll
            for (int p = 0; p < 2; p++) {
                ldsm_x4(bh4[p], bB + SM_BH + p * (16 * B_ROW) + ks * 32);
                ldsm_x4(bl4[p], bB + SM_BL + p * (16 * B_ROW) + ks * 32);
            }
#pragma unroll
            for (int mf = 0; mf < 4; mf++)
#pragma unroll
                for (int nf = 0; nf < 4; nf++) {
                    const uint32_t* bh = &bh4[nf >> 1][(nf & 1) * 2];
                    const uint32_t* bl = &bl4[nf >> 1][(nf & 1) * 2];
                    mma_bf16(acc[mf][nf], ahf[mf], bh);
                    mma_bf16(acc[mf][nf], ahf[mf], bl);
                    mma_bf16(acc[mf][nf], alf[mf], bh);
                }
        }
    }

    // epilogue -> fp16
#pragma unroll
    for (int mf = 0; mf < 4; mf++) {
        int r0 = rowBase + wm * 64 + mf * 16 + (lane >> 2);
#pragma unroll
        for (int nf = 0; nf < 4; nf++) {
            int col = colBase + wn * 32 + nf * 8 + 2 * (lane & 3);
            if (r0 < M)
                *(__half2*)(g_Wh_h + (size_t)r0 * OUT_F + col) =
                    __floats2half2_rn(acc[mf][nf][0], acc[mf][nf][1]);
            if (r0 + 8 < M)
                *(__half2*)(g_Wh_h + (size_t)(r0 + 8) * OUT_F + col) =
                    __floats2half2_rn(acc[mf][nf][2], acc[mf][nf][3]);
        }
    }
}

// ---------------------------------------------------------------------------
// Kernel 2: degree histogram over src   (adj is INT32: [2, E] row-major)
// ---------------------------------------------------------------------------
__global__ void k_count(const int* __restrict__ adj, int E) {
    int e = blockIdx.x * blockDim.x + threadIdx.x;
    if (e < E) atomicAdd(&g_deg[adj[e]], 1);
}

// ---------------------------------------------------------------------------
// Kernels 3-5: exclusive scan of g_deg -> g_rowstart (and g_cursor copy)
// ---------------------------------------------------------------------------
__global__ void k_scan1(int n) {
    __shared__ int sm[SCAN_BLK];
    int i = blockIdx.x * SCAN_BLK + threadIdx.x;
    int v = (i < n) ? g_deg[i] : 0;
    sm[threadIdx.x] = v;
    __syncthreads();
    for (int off = 1; off < SCAN_BLK; off <<= 1) {
        int add = (threadIdx.x >= off) ? sm[threadIdx.x - off] : 0;
        __syncthreads();
        sm[threadIdx.x] += add;
        __syncthreads();
    }
    if (i < n) g_rowstart[i] = sm[threadIdx.x] - v;
    if (threadIdx.x == SCAN_BLK - 1) g_bsum[blockIdx.x] = sm[SCAN_BLK - 1];
}

__global__ void k_scan2(int nb) {
    __shared__ int sm[256];
    int t = threadIdx.x;
    int v = (t < nb) ? g_bsum[t] : 0;
    sm[t] = v;
    __syncthreads();
    for (int off = 1; off < 256; off <<= 1) {
        int add = (t >= off) ? sm[t - off] : 0;
        __syncthreads();
        sm[t] += add;
        __syncthreads();
    }
    if (t < nb) g_bsum[t] = sm[t] - v;
}

__global__ void k_scan3(int n) {
    int i = blockIdx.x * blockDim.x + threadIdx.x;
    if (i < n) {
        int rs = g_rowstart[i] + g_bsum[i >> 9];
        g_rowstart[i] = rs;
        g_cursor[i]   = rs;
    }
}

// ---------------------------------------------------------------------------
// Kernel 6: scatter edges into CSR (dst per slot)
// ---------------------------------------------------------------------------
__global__ void k_scatter(const int* __restrict__ adj, int E) {
    int e = blockIdx.x * blockDim.x + threadIdx.x;
    if (e < E) {
        int s = adj[e];
        int d = adj[E + e];
        int p = atomicAdd(&g_cursor[s], 1);
        g_edst[p] = d;
    }
}

// ---------------------------------------------------------------------------
// Kernel 7a: warp-per-node attention -> normalized weights in g_att
// ---------------------------------------------------------------------------
__global__ __launch_bounds__(256) void k_attention(
    const float* __restrict__ label,   // [N, 32]
    int n)
{
    const int wl   = threadIdx.x >> 5;
    const int lane = threadIdx.x & 31;
    const int w    = blockIdx.x * 8 + wl;
    if (w >= n) return;

    const float labi = label[(size_t)w * D_LABEL + lane];
    const int start = g_rowstart[w];
    const int d     = g_deg[w];

    float denom = 0.0f;
    int k = 0;
    for (; k + 1 < d; k += 2) {
        int j0 = __ldg(g_edst + start + k);
        int j1 = __ldg(g_edst + start + k + 1);
        float v0 = labi * __ldg(label + (size_t)j0 * D_LABEL + lane);
        float v1 = labi * __ldg(label + (size_t)j1 * D_LABEL + lane);
#pragma unroll
        for (int o = 16; o > 0; o >>= 1) {
            v0 += __shfl_xor_sync(0xffffffffu, v0, o);
            v1 += __shfl_xor_sync(0xffffffffu, v1, o);
        }
        float e0 = (v0 >= 0.0f) ? v0 : ALPHA * v0;
        float e1 = (v1 >= 0.0f) ? v1 : ALPHA * v1;
        float ex0 = __expf(e0);
        float ex1 = __expf(e1);
        denom += ex0 + ex1;
        if (lane == (k & 31))       g_att[start + k]     = ex0;
        if (lane == ((k + 1) & 31)) g_att[start + k + 1] = ex1;
    }
    if (k < d) {
        int j0 = __ldg(g_edst + start + k);
        float v0 = labi * __ldg(label + (size_t)j0 * D_LABEL + lane);
#pragma unroll
        for (int o = 16; o > 0; o >>= 1)
            v0 += __shfl_xor_sync(0xffffffffu, v0, o);
        float e0 = (v0 >= 0.0f) ? v0 : ALPHA * v0;
        float ex0 = __expf(e0);
        denom += ex0;
        if (lane == (k & 31)) g_att[start + k] = ex0;
    }
    const float inv = 1.0f / fmaxf(denom, EPS_RS);
    for (int t = lane; t < d; t += 32)
        g_att[start + t] *= inv;
}

// ---------------------------------------------------------------------------
// Kernel 7b: gather — exact R7 form (proven best: 353us total config)
// 1 warp per node; lane covers 8 cols (uint4 of fp16); 4 edges in flight
// ---------------------------------------------------------------------------
__device__ __forceinline__ void fma8_h(float* acc, uint4 v, float a) {
    float2 f;
    f = __half22float2(*(__half2*)&v.x);
    acc[0] = fmaf(a, f.x, acc[0]); acc[1] = fmaf(a, f.y, acc[1]);
    f = __half22float2(*((__half2*)&v.x + 1));
    acc[2] = fmaf(a, f.x, acc[2]); acc[3] = fmaf(a, f.y, acc[3]);
    f = __half22float2(*(__half2*)&v.z);
    acc[4] = fmaf(a, f.x, acc[4]); acc[5] = fmaf(a, f.y, acc[5]);
    f = __half22float2(*((__half2*)&v.z + 1));
    acc[6] = fmaf(a, f.x, acc[6]); acc[7] = fmaf(a, f.y, acc[7]);
}

__global__ __launch_bounds__(256) void k_gather(
    float* __restrict__ out,   // [N, 256]
    int n)
{
    const int w    = blockIdx.x * 8 + (threadIdx.x >> 5);
    const int lane = threadIdx.x & 31;
    if (w >= n) return;

    const int start = g_rowstart[w];
    const int d     = g_deg[w];
    const __half* base = g_Wh_h + lane * 8;   // 16B per lane, 512B per warp row

    float acc[8];
#pragma unroll
    for (int q = 0; q < 8; q++) acc[q] = 0.0f;

    int k = 0;
    for (; k + 3 < d; k += 4) {
        int j0 = __ldg(g_edst + start + k);
        int j1 = __ldg(g_edst + start + k + 1);
        int j2 = __ldg(g_edst + start + k + 2);
        int j3 = __ldg(g_edst + start + k + 3);
        float a0 = __ldg(g_att + start + k);
        float a1 = __ldg(g_att + start + k + 1);
        float a2 = __ldg(g_att + start + k + 2);
        float a3 = __ldg(g_att + start + k + 3);
        uint4 v0 = __ldg((const uint4*)(base + (size_t)j0 * OUT_F));
        uint4 v1 = __ldg((const uint4*)(base + (size_t)j1 * OUT_F));
        uint4 v2 = __ldg((const uint4*)(base + (size_t)j2 * OUT_F));
        uint4 v3 = __ldg((const uint4*)(base + (size_t)j3 * OUT_F));
        fma8_h(acc, v0, a0);
        fma8_h(acc, v1, a1);
        fma8_h(acc, v2, a2);
        fma8_h(acc, v3, a3);
    }
    for (; k < d; k++) {
        int j0 = __ldg(g_edst + start + k);
        float a0 = __ldg(g_att + start + k);
        uint4 v0 = __ldg((const uint4*)(base + (size_t)j0 * OUT_F));
        fma8_h(acc, v0, a0);
    }

    float* o = out + (size_t)w * OUT_F + lane * 8;
    *(float4*)(o + 0) = make_float4(acc[0], acc[1], acc[2], acc[3]);
    *(float4*)(o + 4) = make_float4(acc[4], acc[5], acc[6], acc[7]);
}

// ---------------------------------------------------------------------------
// Launch — stream fork: branch A = prep_W + GEMM (default stream),
//                        branch B = CSR build + attention (s2), join -> gather
// ---------------------------------------------------------------------------
extern "C" void kernel_launch(void* const* d_in, const int* in_sizes, int n_in,
                              void* d_out, int out_size)
{
    const float* h     = (const float*)d_in[0];   // [N, 256] fp32
    const float* label = (const float*)d_in[1];   // [N, 32]  fp32
    const float* W     = (const float*)d_in[2];   // [256, 256] fp32
    const int*   adj   = (const int*)d_in[3];     // [2, E] int32
    float*       out   = (float*)d_out;

    const int N = in_sizes[0] / IN_F;      // 100000
    const int E = in_sizes[3] / 2;         // 1600000

    const int T = 256;
    const int gbN = (N + T - 1) / T;
    const int gbE = (E + T - 1) / T;

    static cudaStream_t s2 = nullptr;
    static cudaEvent_t  evF = nullptr, evJ = nullptr;
    if (s2 == nullptr) {
        cudaFuncSetAttribute(k_gemm_mma, cudaFuncAttributeMaxDynamicSharedMemorySize, GSM_TOTAL);
        cudaStreamCreateWithFlags(&s2, cudaStreamNonBlocking);
        cudaEventCreateWithFlags(&evF, cudaEventDisableTiming);
        cudaEventCreateWithFlags(&evJ, cudaEventDisableTiming);
    }

    // fork
    cudaEventRecord(evF, 0);
    cudaStreamWaitEvent(s2, evF, 0);

    // ---- branch B (s2): CSR build + attention weights
    k_zero_deg<<<gbN, T, 0, s2>>>(N);
    k_count<<<gbE, T, 0, s2>>>(adj, E);
    int nb = (N + SCAN_BLK - 1) / SCAN_BLK;
    k_scan1<<<nb, SCAN_BLK, 0, s2>>>(N);
    k_scan2<<<1, 256, 0, s2>>>(nb);
    k_scan3<<<gbN, T, 0, s2>>>(N);
    k_scatter<<<gbE, T, 0, s2>>>(adj, E);
    k_attention<<<(N + 7) / 8, 256, 0, s2>>>(label, N);
    cudaEventRecord(evJ, s2);

    // ---- branch A (default stream): GEMM (R7 tile config: grid.x = 2)
    k_prep_W<<<256, 256>>>(W);
    dim3 ggrid(2, (N + 127) / 128);
    k_gemm_mma<<<ggrid, 256, GSM_TOTAL>>>(h, N);

    // join, then gather
    cudaStreamWaitEvent(0, evJ, 0);
    k_gather<<<(N + 7) / 8, 256>>>(out, N);
}

// round 11
// speedup vs baseline: 1.1423x; 1.0710x over previous
#include <cuda_runtime.h>
#include <cuda_bf16.h>
#include <cuda_fp16.h>
#include <math.h>
#include <stdint.h>

// Problem constants (fixed by the dataset)
#define N_NODES   100000
#define N_EDGES   1600000
#define IN_F      256
#define OUT_F     256
#define D_LABEL   32
#define ALPHA     0.2f
#define EPS_RS    1e-9f

#define SCAN_BLK  512

// Scratch (device globals: allowed; no cudaMalloc anywhere)
__device__ __half g_Wh_h[(size_t)N_NODES * OUT_F];   // ~50 MB (fp16 Wh)
__device__ float g_att[N_EDGES];
__device__ int   g_deg[N_NODES];
__device__ int   g_rowstart[N_NODES];
__device__ int   g_cursor[N_NODES];
__device__ int   g_edst[N_EDGES];
__device__ int   g_bsum[256];
// W transposed + bf16 split: Wt[n][k] = W[k][n]
__device__ __nv_bfloat16 g_Wt_hi[256 * 256];
__device__ __nv_bfloat16 g_Wt_lo[256 * 256];

// ---------------------------------------------------------------------------
// helpers
// ---------------------------------------------------------------------------
__device__ __forceinline__ uint32_t smem_u32(const void* p) {
    uint32_t a;
    asm("{ .reg .u64 t; cvta.to.shared.u64 t, %1; cvt.u32.u64 %0, t; }"
        : "=r"(a) : "l"(p));
    return a;
}

__device__ __forceinline__ void ldsm_x4(uint32_t* r, uint32_t addr) {
    asm volatile("ldmatrix.sync.aligned.m8n8.x4.shared.b16 {%0,%1,%2,%3}, [%4];"
                 : "=r"(r[0]), "=r"(r[1]), "=r"(r[2]), "=r"(r[3]) : "r"(addr));
}
__device__ __forceinline__ void mma_bf16(float* c, const uint32_t* a, const uint32_t* b) {
    asm volatile(
        "mma.sync.aligned.m16n8k16.row.col.f32.bf16.bf16.f32 "
        "{%0,%1,%2,%3}, {%4,%5,%6,%7}, {%8,%9}, {%0,%1,%2,%3};"
        : "+f"(c[0]), "+f"(c[1]), "+f"(c[2]), "+f"(c[3])
        : "r"(a[0]), "r"(a[1]), "r"(a[2]), "r"(a[3]), "r"(b[0]), "r"(b[1]));
}

// ---------------------------------------------------------------------------
// Kernel 0: zero degree array
// ---------------------------------------------------------------------------
__global__ void k_zero_deg(int n) {
    int i = blockIdx.x * blockDim.x + threadIdx.x;
    if (i < n) g_deg[i] = 0;
}

// ---------------------------------------------------------------------------
// Kernel P: W [K,N] fp32 -> Wt_hi/Wt_lo [N,K] bf16 split
// ---------------------------------------------------------------------------
__global__ void k_prep_W(const float* __restrict__ W) {
    int i = blockIdx.x * 256 + threadIdx.x;     // 0..65535
    int n = i >> 8, k = i & 255;
    float w = W[k * 256 + n];
    __nv_bfloat16 hi = __float2bfloat16(w);
    __nv_bfloat16 lo = __float2bfloat16(w - __bfloat162float(hi));
    g_Wt_hi[n * 256 + k] = hi;
    g_Wt_lo[n * 256 + k] = lo;
}

// ---------------------------------------------------------------------------
// Kernel 1: HMMA GEMM  Wh = h @ W  via bf16 hi/lo split (3 products)
// R11: CTA 128M x 256N, 512 threads (16 warps, grid 4x4, warp tile 32x64).
// A read ONCE (grid.y only). Both A and B chunk-staged (K chunks of 32) in
// 80B-pitch rows, double-buffered, register-prefetched. smem 120KB.
// ---------------------------------------------------------------------------
#define C_ROW 80
#define ST_AH 0                    // A_hi 128*80 = 10240
#define ST_AL 10240                // A_lo
#define ST_BH 20480                // B_hi 256*80 = 20480
#define ST_BL 40960                // B_lo
#define STAGE_SZ 61440
#define GSM_TOTAL (2 * STAGE_SZ)   // 122880

__global__ __launch_bounds__(512, 1) void k_gemm_mma(const float* __restrict__ A, int M)
{
    extern __shared__ __align__(16) char sm[];
    const uint32_t sbase = smem_u32(sm);
    const int tid  = threadIdx.x;
    const int lane = tid & 31;
    const int wid  = tid >> 5;          // 0..15
    const int wm   = wid >> 2;          // 0..3
    const int wn   = wid & 3;           // 0..3
    const int rowBase = blockIdx.y * 128;

    float acc[2][8][4];
#pragma unroll
    for (int i = 0; i < 2; i++)
#pragma unroll
        for (int j = 0; j < 8; j++)
#pragma unroll
            for (int q = 0; q < 4; q++) acc[i][j][q] = 0.0f;

    // ---- A fill mapping: thread -> (row, quarter of 32-float chunk)
    const int ar = tid >> 2;            // 0..127
    const int aq = tid & 3;             // 0..3 (8 floats)
    const int grow = rowBase + ar;
    const float* aptr = A + (size_t)grow * IN_F + aq * 8;

    // ---- B fill mapping: 2 slots per thread: i = tid, tid+512 -> (n, q)
    const int bn0 = tid >> 2;           // 0..127
    const int bn1 = (tid + 512) >> 2;   // 128..255
    const int bq  = tid & 3;

    // prefetch chunk 0
    float4 pfA0 = make_float4(0.f,0.f,0.f,0.f), pfA1 = pfA0;
    if (grow < M) {
        pfA0 = *(const float4*)(aptr + 0);
        pfA1 = *(const float4*)(aptr + 4);
    }
    uint4 pfBh0 = *(const uint4*)((const char*)g_Wt_hi + (size_t)bn0 * 512 + bq * 16);
    uint4 pfBh1 = *(const uint4*)((const char*)g_Wt_hi + (size_t)bn1 * 512 + bq * 16);
    uint4 pfBl0 = *(const uint4*)((const char*)g_Wt_lo + (size_t)bn0 * 512 + bq * 16);
    uint4 pfBl1 = *(const uint4*)((const char*)g_Wt_lo + (size_t)bn1 * 512 + bq * 16);

    // fragment address bases
    const uint32_t a_frag_off = (uint32_t)((wm * 32 + (lane & 15)) * C_ROW + (lane >> 4) * 16);
    const uint32_t b4_frag_off = (uint32_t)(
        (wn * 64 + (lane & 7) + ((lane >> 4) & 1) * 8) * C_ROW + ((lane >> 3) & 1) * 16);
    const uint32_t a_sts = (uint32_t)(ar * C_ROW + aq * 16);
    const uint32_t b_sts0 = (uint32_t)(bn0 * C_ROW + bq * 16);
    const uint32_t b_sts1 = (uint32_t)(bn1 * C_ROW + bq * 16);

    for (int c = 0; c < 8; c++) {
        const int stage = c & 1;
        char* stg = sm + stage * STAGE_SZ;
        // ---- store A (convert fp32 -> bf16 hi/lo)
        {
            float x[8] = { pfA0.x, pfA0.y, pfA0.z, pfA0.w, pfA1.x, pfA1.y, pfA1.z, pfA1.w };
            uint32_t hv[4], lv[4];
#pragma unroll
            for (int e = 0; e < 4; e++) {
                float f0 = x[e * 2], f1 = x[e * 2 + 1];
                __nv_bfloat16 h0 = __float2bfloat16(f0);
                __nv_bfloat16 h1 = __float2bfloat16(f1);
                __nv_bfloat16 l0 = __float2bfloat16(f0 - __bfloat162float(h0));
                __nv_bfloat16 l1 = __float2bfloat16(f1 - __bfloat162float(h1));
                hv[e] = (uint32_t)__bfloat16_as_ushort(h0) |
                        ((uint32_t)__bfloat16_as_ushort(h1) << 16);
                lv[e] = (uint32_t)__bfloat16_as_ushort(l0) |
                        ((uint32_t)__bfloat16_as_ushort(l1) << 16);
            }
            *(uint4*)(stg + ST_AH + a_sts) = make_uint4(hv[0], hv[1], hv[2], hv[3]);
            *(uint4*)(stg + ST_AL + a_sts) = make_uint4(lv[0], lv[1], lv[2], lv[3]);
        }
        // ---- store B (already bf16)
        *(uint4*)(stg + ST_BH + b_sts0) = pfBh0;
        *(uint4*)(stg + ST_BH + b_sts1) = pfBh1;
        *(uint4*)(stg + ST_BL + b_sts0) = pfBl0;
        *(uint4*)(stg + ST_BL + b_sts1) = pfBl1;
        __syncthreads();

        // ---- prefetch next chunk
        if (c < 7) {
            if (grow < M) {
                pfA0 = *(const float4*)(aptr + (c + 1) * 32 + 0);
                pfA1 = *(const float4*)(aptr + (c + 1) * 32 + 4);
            }
            pfBh0 = *(const uint4*)((const char*)g_Wt_hi + (size_t)bn0 * 512 + (c + 1) * 64 + bq * 16);
            pfBh1 = *(const uint4*)((const char*)g_Wt_hi + (size_t)bn1 * 512 + (c + 1) * 64 + bq * 16);
            pfBl0 = *(const uint4*)((const char*)g_Wt_lo + (size_t)bn0 * 512 + (c + 1) * 64 + bq * 16);
            pfBl1 = *(const uint4*)((const char*)g_Wt_lo + (size_t)bn1 * 512 + (c + 1) * 64 + bq * 16);
        }

        // ---- compute chunk
        const uint32_t aB = sbase + stage * STAGE_SZ + a_frag_off;
        const uint32_t bB = sbase + stage * STAGE_SZ + b4_frag_off;
#pragma unroll
        for (int ks = 0; ks < 2; ks++) {
            uint32_t ahf[2][4], alf[2][4];
#pragma unroll
            for (int mf = 0; mf < 2; mf++) {
                ldsm_x4(ahf[mf], aB + ST_AH + mf * (16 * C_ROW) + ks * 32);
                ldsm_x4(alf[mf], aB + ST_AL + mf * (16 * C_ROW) + ks * 32);
            }
#pragma unroll
            for (int p = 0; p < 4; p++) {
                uint32_t bh4[4], bl4[4];
                ldsm_x4(bh4, bB + ST_BH + p * (16 * C_ROW) + ks * 32);
                ldsm_x4(bl4, bB + ST_BL + p * (16 * C_ROW) + ks * 32);
#pragma unroll
                for (int mf = 0; mf < 2; mf++)
#pragma unroll
                    for (int h = 0; h < 2; h++) {
                        float* a4 = acc[mf][2 * p + h];
                        mma_bf16(a4, ahf[mf], &bh4[h * 2]);
                        mma_bf16(a4, ahf[mf], &bl4[h * 2]);
                        mma_bf16(a4, alf[mf], &bh4[h * 2]);
                    }
            }
        }
        __syncthreads();
    }

    // epilogue -> fp16
#pragma unroll
    for (int mf = 0; mf < 2; mf++) {
        int r0 = rowBase + wm * 32 + mf * 16 + (lane >> 2);
#pragma unroll
        for (int nf = 0; nf < 8; nf++) {
            int col = wn * 64 + nf * 8 + 2 * (lane & 3);
            if (r0 < M)
                *(__half2*)(g_Wh_h + (size_t)r0 * OUT_F + col) =
                    __floats2half2_rn(acc[mf][nf][0], acc[mf][nf][1]);
            if (r0 + 8 < M)
                *(__half2*)(g_Wh_h + (size_t)(r0 + 8) * OUT_F + col) =
                    __floats2half2_rn(acc[mf][nf][2], acc[mf][nf][3]);
        }
    }
}

// ---------------------------------------------------------------------------
// Kernel 2: degree histogram over src   (adj is INT32: [2, E] row-major)
// ---------------------------------------------------------------------------
__global__ void k_count(const int* __restrict__ adj, int E) {
    int e = blockIdx.x * blockDim.x + threadIdx.x;
    if (e < E) atomicAdd(&g_deg[adj[e]], 1);
}

// ---------------------------------------------------------------------------
// Kernels 3-5: exclusive scan of g_deg -> g_rowstart (and g_cursor copy)
// ---------------------------------------------------------------------------
__global__ void k_scan1(int n) {
    __shared__ int sm[SCAN_BLK];
    int i = blockIdx.x * SCAN_BLK + threadIdx.x;
    int v = (i < n) ? g_deg[i] : 0;
    sm[threadIdx.x] = v;
    __syncthreads();
    for (int off = 1; off < SCAN_BLK; off <<= 1) {
        int add = (threadIdx.x >= off) ? sm[threadIdx.x - off] : 0;
        __syncthreads();
        sm[threadIdx.x] += add;
        __syncthreads();
    }
    if (i < n) g_rowstart[i] = sm[threadIdx.x] - v;
    if (threadIdx.x == SCAN_BLK - 1) g_bsum[blockIdx.x] = sm[SCAN_BLK - 1];
}

__global__ void k_scan2(int nb) {
    __shared__ int sm[256];
    int t = threadIdx.x;
    int v = (t < nb) ? g_bsum[t] : 0;
    sm[t] = v;
    __syncthreads();
    for (int off = 1; off < 256; off <<= 1) {
        int add = (t >= off) ? sm[t - off] : 0;
        __syncthreads();
        sm[t] += add;
        __syncthreads();
    }
    if (t < nb) g_bsum[t] = sm[t] - v;
}

__global__ void k_scan3(int n) {
    int i = blockIdx.x * blockDim.x + threadIdx.x;
    if (i < n) {
        int rs = g_rowstart[i] + g_bsum[i >> 9];
        g_rowstart[i] = rs;
        g_cursor[i]   = rs;
    }
}

// ---------------------------------------------------------------------------
// Kernel 6: scatter edges into CSR (dst per slot)
// ---------------------------------------------------------------------------
__global__ void k_scatter(const int* __restrict__ adj, int E) {
    int e = blockIdx.x * blockDim.x + threadIdx.x;
    if (e < E) {
        int s = adj[e];
        int d = adj[E + e];
        int p = atomicAdd(&g_cursor[s], 1);
        g_edst[p] = d;
    }
}

// ---------------------------------------------------------------------------
// Kernel 7a: warp-per-node attention -> normalized weights in g_att
// ---------------------------------------------------------------------------
__global__ __launch_bounds__(256) void k_attention(
    const float* __restrict__ label,   // [N, 32]
    int n)
{
    const int wl   = threadIdx.x >> 5;
    const int lane = threadIdx.x & 31;
    const int w    = blockIdx.x * 8 + wl;
    if (w >= n) return;

    const float labi = label[(size_t)w * D_LABEL + lane];
    const int start = g_rowstart[w];
    const int d     = g_deg[w];

    float denom = 0.0f;
    int k = 0;
    for (; k + 1 < d; k += 2) {
        int j0 = __ldg(g_edst + start + k);
        int j1 = __ldg(g_edst + start + k + 1);
        float v0 = labi * __ldg(label + (size_t)j0 * D_LABEL + lane);
        float v1 = labi * __ldg(label + (size_t)j1 * D_LABEL + lane);
#pragma unroll
        for (int o = 16; o > 0; o >>= 1) {
            v0 += __shfl_xor_sync(0xffffffffu, v0, o);
            v1 += __shfl_xor_sync(0xffffffffu, v1, o);
        }
        float e0 = (v0 >= 0.0f) ? v0 : ALPHA * v0;
        float e1 = (v1 >= 0.0f) ? v1 : ALPHA * v1;
        float ex0 = __expf(e0);
        float ex1 = __expf(e1);
        denom += ex0 + ex1;
        if (lane == (k & 31))       g_att[start + k]     = ex0;
        if (lane == ((k + 1) & 31)) g_att[start + k + 1] = ex1;
    }
    if (k < d) {
        int j0 = __ldg(g_edst + start + k);
        float v0 = labi * __ldg(label + (size_t)j0 * D_LABEL + lane);
#pragma unroll
        for (int o = 16; o > 0; o >>= 1)
            v0 += __shfl_xor_sync(0xffffffffu, v0, o);
        float e0 = (v0 >= 0.0f) ? v0 : ALPHA * v0;
        float ex0 = __expf(e0);
        denom += ex0;
        if (lane == (k & 31)) g_att[start + k] = ex0;
    }
    const float inv = 1.0f / fmaxf(denom, EPS_RS);
    for (int t = lane; t < d; t += 32)
        g_att[start + t] *= inv;
}

// ---------------------------------------------------------------------------
// Kernel 7b: gather — exact R7 form (proven best)
// 1 warp per node; lane covers 8 cols (uint4 of fp16); 4 edges in flight
// ---------------------------------------------------------------------------
__device__ __forceinline__ void fma8_h(float* acc, uint4 v, float a) {
    float2 f;
    f = __half22float2(*(__half2*)&v.x);
    acc[0] = fmaf(a, f.x, acc[0]); acc[1] = fmaf(a, f.y, acc[1]);
    f = __half22float2(*((__half2*)&v.x + 1));
    acc[2] = fmaf(a, f.x, acc[2]); acc[3] = fmaf(a, f.y, acc[3]);
    f = __half22float2(*(__half2*)&v.z);
    acc[4] = fmaf(a, f.x, acc[4]); acc[5] = fmaf(a, f.y, acc[5]);
    f = __half22float2(*((__half2*)&v.z + 1));
    acc[6] = fmaf(a, f.x, acc[6]); acc[7] = fmaf(a, f.y, acc[7]);
}

__global__ __launch_bounds__(256) void k_gather(
    float* __restrict__ out,   // [N, 256]
    int n)
{
    const int w    = blockIdx.x * 8 + (threadIdx.x >> 5);
    const int lane = threadIdx.x & 31;
    if (w >= n) return;

    const int start = g_rowstart[w];
    const int d     = g_deg[w];
    const __half* base = g_Wh_h + lane * 8;   // 16B per lane, 512B per warp row

    float acc[8];
#pragma unroll
    for (int q = 0; q < 8; q++) acc[q] = 0.0f;

    int k = 0;
    for (; k + 3 < d; k += 4) {
        int j0 = __ldg(g_edst + start + k);
        int j1 = __ldg(g_edst + start + k + 1);
        int j2 = __ldg(g_edst + start + k + 2);
        int j3 = __ldg(g_edst + start + k + 3);
        float a0 = __ldg(g_att + start + k);
        float a1 = __ldg(g_att + start + k + 1);
        float a2 = __ldg(g_att + start + k + 2);
        float a3 = __ldg(g_att + start + k + 3);
        uint4 v0 = __ldg((const uint4*)(base + (size_t)j0 * OUT_F));
        uint4 v1 = __ldg((const uint4*)(base + (size_t)j1 * OUT_F));
        uint4 v2 = __ldg((const uint4*)(base + (size_t)j2 * OUT_F));
        uint4 v3 = __ldg((const uint4*)(base + (size_t)j3 * OUT_F));
        fma8_h(acc, v0, a0);
        fma8_h(acc, v1, a1);
        fma8_h(acc, v2, a2);
        fma8_h(acc, v3, a3);
    }
    for (; k < d; k++) {
        int j0 = __ldg(g_edst + start + k);
        float a0 = __ldg(g_att + start + k);
        uint4 v0 = __ldg((const uint4*)(base + (size_t)j0 * OUT_F));
        fma8_h(acc, v0, a0);
    }

    float* o = out + (size_t)w * OUT_F + lane * 8;
    *(float4*)(o + 0) = make_float4(acc[0], acc[1], acc[2], acc[3]);
    *(float4*)(o + 4) = make_float4(acc[4], acc[5], acc[6], acc[7]);
}

// ---------------------------------------------------------------------------
// Launch — stream fork: branch A = prep_W + GEMM (default stream),
//                        branch B = CSR build + attention (s2), join -> gather
// ---------------------------------------------------------------------------
extern "C" void kernel_launch(void* const* d_in, const int* in_sizes, int n_in,
                              void* d_out, int out_size)
{
    const float* h     = (const float*)d_in[0];   // [N, 256] fp32
    const float* label = (const float*)d_in[1];   // [N, 32]  fp32
    const float* W     = (const float*)d_in[2];   // [256, 256] fp32
    const int*   adj   = (const int*)d_in[3];     // [2, E] int32
    float*       out   = (float*)d_out;

    const int N = in_sizes[0] / IN_F;      // 100000
    const int E = in_sizes[3] / 2;         // 1600000

    const int T = 256;
    const int gbN = (N + T - 1) / T;
    const int gbE = (E + T - 1) / T;

    static cudaStream_t s2 = nullptr;
    static cudaEvent_t  evF = nullptr, evJ = nullptr;
    if (s2 == nullptr) {
        cudaFuncSetAttribute(k_gemm_mma, cudaFuncAttributeMaxDynamicSharedMemorySize, GSM_TOTAL);
        cudaStreamCreateWithFlags(&s2, cudaStreamNonBlocking);
        cudaEventCreateWithFlags(&evF, cudaEventDisableTiming);
        cudaEventCreateWithFlags(&evJ, cudaEventDisableTiming);
    }

    // fork
    cudaEventRecord(evF, 0);
    cudaStreamWaitEvent(s2, evF, 0);

    // ---- branch B (s2): CSR build + attention weights
    k_zero_deg<<<gbN, T, 0, s2>>>(N);
    k_count<<<gbE, T, 0, s2>>>(adj, E);
    int nb = (N + SCAN_BLK - 1) / SCAN_BLK;
    k_scan1<<<nb, SCAN_BLK, 0, s2>>>(N);
    k_scan2<<<1, 256, 0, s2>>>(nb);
    k_scan3<<<gbN, T, 0, s2>>>(N);
    k_scatter<<<gbE, T, 0, s2>>>(adj, E);
    k_attention<<<(N + 7) / 8, 256, 0, s2>>>(label, N);
    cudaEventRecord(evJ, s2);

    // ---- branch A (default stream): GEMM (full-N CTA, A read once)
    k_prep_W<<<256, 256>>>(W);
    dim3 ggrid(1, (N + 127) / 128);
    k_gemm_mma<<<ggrid, 512, GSM_TOTAL>>>(h, N);

    // join, then gather
    cudaStreamWaitEvent(0, evJ, 0);
    k_gather<<<(N + 7) / 8, 256>>>(out, N);
}

// round 12
// speedup vs baseline: 1.2917x; 1.1308x over previous
#include <cuda_runtime.h>
#include <cuda_bf16.h>
#include <cuda_fp16.h>
#include <math.h>
#include <stdint.h>

// Problem constants (fixed by the dataset)
#define N_NODES   100000
#define N_EDGES   1600000
#define IN_F      256
#define OUT_F     256
#define D_LABEL   32
#define ALPHA     0.2f
#define EPS_RS    1e-9f

#define SCAN_BLK  512

// Scratch (device globals: allowed; no cudaMalloc anywhere)
__device__ __half g_Wh_h[(size_t)N_NODES * OUT_F];   // ~50 MB (fp16 Wh)
__device__ float g_att[N_EDGES];
__device__ int   g_deg[N_NODES];
__device__ int   g_rowstart[N_NODES];
__device__ int   g_cursor[N_NODES];
__device__ int   g_edst[N_EDGES];
__device__ int   g_bsum[256];
// W transposed + fp16 hi/lo split: Wt[n][k] = W[k][n]
__device__ __half g_Wt16_hi[256 * 256];
__device__ __half g_Wt16_lo[256 * 256];

// ---------------------------------------------------------------------------
// helpers
// ---------------------------------------------------------------------------
__device__ __forceinline__ uint32_t smem_u32(const void* p) {
    uint32_t a;
    asm("{ .reg .u64 t; cvta.to.shared.u64 t, %1; cvt.u32.u64 %0, t; }"
        : "=r"(a) : "l"(p));
    return a;
}

__device__ __forceinline__ void ldsm_x4(uint32_t* r, uint32_t addr) {
    asm volatile("ldmatrix.sync.aligned.m8n8.x4.shared.b16 {%0,%1,%2,%3}, [%4];"
                 : "=r"(r[0]), "=r"(r[1]), "=r"(r[2]), "=r"(r[3]) : "r"(addr));
}
__device__ __forceinline__ void mma_fp16(float* c, const uint32_t* a, const uint32_t* b) {
    asm volatile(
        "mma.sync.aligned.m16n8k16.row.col.f32.f16.f16.f32 "
        "{%0,%1,%2,%3}, {%4,%5,%6,%7}, {%8,%9}, {%0,%1,%2,%3};"
        : "+f"(c[0]), "+f"(c[1]), "+f"(c[2]), "+f"(c[3])
        : "r"(a[0]), "r"(a[1]), "r"(a[2]), "r"(a[3]), "r"(b[0]), "r"(b[1]));
}

// ---------------------------------------------------------------------------
// Kernel 0: zero degree array
// ---------------------------------------------------------------------------
__global__ void k_zero_deg(int n) {
    int i = blockIdx.x * blockDim.x + threadIdx.x;
    if (i < n) g_deg[i] = 0;
}

// ---------------------------------------------------------------------------
// Kernel P: W [K,N] fp32 -> Wt16_hi/Wt16_lo [N,K] fp16 split
// ---------------------------------------------------------------------------
__global__ void k_prep_W(const float* __restrict__ W) {
    int i = blockIdx.x * 256 + threadIdx.x;     // 0..65535
    int n = i >> 8, k = i & 255;
    float w = W[k * 256 + n];
    __half hi = __float2half_rn(w);
    __half lo = __float2half_rn(w - __half2float(hi));
    g_Wt16_hi[n * 256 + k] = hi;
    g_Wt16_lo[n * 256 + k] = lo;
}

// ---------------------------------------------------------------------------
// Kernel 1: HMMA GEMM  Wh = h @ W, fp16 scheme:
//   A fp16 (single), B fp16 hi/lo -> 2 products: A*Bh + A*Bl
// CTA 128M x 256N, 512 threads (warp grid 4x4, warp tile 32x64), A read once,
// both operands chunk-staged (K chunks of 32), double-buffered. smem 100KB.
// ---------------------------------------------------------------------------
#define C_ROW 80
#define ST_A  0                    // A   128*80 = 10240
#define ST_BH 10240                // B_hi 256*80 = 20480
#define ST_BL 30720                // B_lo
#define STAGE_SZ 51200
#define GSM_TOTAL (2 * STAGE_SZ)   // 102400

__global__ __launch_bounds__(512, 1) void k_gemm_mma(const float* __restrict__ A, int M)
{
    extern __shared__ __align__(16) char sm[];
    const uint32_t sbase = smem_u32(sm);
    const int tid  = threadIdx.x;
    const int lane = tid & 31;
    const int wid  = tid >> 5;          // 0..15
    const int wm   = wid >> 2;          // 0..3
    const int wn   = wid & 3;           // 0..3
    const int rowBase = blockIdx.y * 128;

    float acc[2][8][4];
#pragma unroll
    for (int i = 0; i < 2; i++)
#pragma unroll
        for (int j = 0; j < 8; j++)
#pragma unroll
            for (int q = 0; q < 4; q++) acc[i][j][q] = 0.0f;

    // ---- A fill mapping: thread -> (row, quarter of 32-float chunk)
    const int ar = tid >> 2;            // 0..127
    const int aq = tid & 3;             // 0..3 (8 floats -> 8 fp16 = 16B)
    const int grow = rowBase + ar;
    const float* aptr = A + (size_t)grow * IN_F + aq * 8;

    // ---- B fill mapping: 2 slots per thread: i = tid, tid+512 -> (n, q)
    const int bn0 = tid >> 2;           // 0..127
    const int bn1 = (tid + 512) >> 2;   // 128..255
    const int bq  = tid & 3;

    // prefetch chunk 0
    float4 pfA0 = make_float4(0.f,0.f,0.f,0.f), pfA1 = pfA0;
    if (grow < M) {
        pfA0 = *(const float4*)(aptr + 0);
        pfA1 = *(const float4*)(aptr + 4);
    }
    uint4 pfBh0 = *(const uint4*)((const char*)g_Wt16_hi + (size_t)bn0 * 512 + bq * 16);
    uint4 pfBh1 = *(const uint4*)((const char*)g_Wt16_hi + (size_t)bn1 * 512 + bq * 16);
    uint4 pfBl0 = *(const uint4*)((const char*)g_Wt16_lo + (size_t)bn0 * 512 + bq * 16);
    uint4 pfBl1 = *(const uint4*)((const char*)g_Wt16_lo + (size_t)bn1 * 512 + bq * 16);

    // fragment address bases
    const uint32_t a_frag_off = (uint32_t)((wm * 32 + (lane & 15)) * C_ROW + (lane >> 4) * 16);
    const uint32_t b4_frag_off = (uint32_t)(
        (wn * 64 + (lane & 7) + ((lane >> 4) & 1) * 8) * C_ROW + ((lane >> 3) & 1) * 16);
    const uint32_t a_sts = (uint32_t)(ar * C_ROW + aq * 16);
    const uint32_t b_sts0 = (uint32_t)(bn0 * C_ROW + bq * 16);
    const uint32_t b_sts1 = (uint32_t)(bn1 * C_ROW + bq * 16);

    for (int c = 0; c < 8; c++) {
        const int stage = c & 1;
        char* stg = sm + stage * STAGE_SZ;
        // ---- store A (convert fp32 -> fp16)
        {
            __half2 p0 = __floats2half2_rn(pfA0.x, pfA0.y);
            __half2 p1 = __floats2half2_rn(pfA0.z, pfA0.w);
            __half2 p2 = __floats2half2_rn(pfA1.x, pfA1.y);
            __half2 p3 = __floats2half2_rn(pfA1.z, pfA1.w);
            uint4 v;
            v.x = *(uint32_t*)&p0; v.y = *(uint32_t*)&p1;
            v.z = *(uint32_t*)&p2; v.w = *(uint32_t*)&p3;
            *(uint4*)(stg + ST_A + a_sts) = v;
        }
        // ---- store B (already fp16 hi/lo)
        *(uint4*)(stg + ST_BH + b_sts0) = pfBh0;
        *(uint4*)(stg + ST_BH + b_sts1) = pfBh1;
        *(uint4*)(stg + ST_BL + b_sts0) = pfBl0;
        *(uint4*)(stg + ST_BL + b_sts1) = pfBl1;
        __syncthreads();

        // ---- prefetch next chunk
        if (c < 7) {
            if (grow < M) {
                pfA0 = *(const float4*)(aptr + (c + 1) * 32 + 0);
                pfA1 = *(const float4*)(aptr + (c + 1) * 32 + 4);
            }
            pfBh0 = *(const uint4*)((const char*)g_Wt16_hi + (size_t)bn0 * 512 + (c + 1) * 64 + bq * 16);
            pfBh1 = *(const uint4*)((const char*)g_Wt16_hi + (size_t)bn1 * 512 + (c + 1) * 64 + bq * 16);
            pfBl0 = *(const uint4*)((const char*)g_Wt16_lo + (size_t)bn0 * 512 + (c + 1) * 64 + bq * 16);
            pfBl1 = *(const uint4*)((const char*)g_Wt16_lo + (size_t)bn1 * 512 + (c + 1) * 64 + bq * 16);
        }

        // ---- compute chunk
        const uint32_t aB = sbase + stage * STAGE_SZ + a_frag_off;
        const uint32_t bB = sbase + stage * STAGE_SZ + b4_frag_off;
#pragma unroll
        for (int ks = 0; ks < 2; ks++) {
            uint32_t ahf[2][4];
#pragma unroll
            for (int mf = 0; mf < 2; mf++)
                ldsm_x4(ahf[mf], aB + ST_A + mf * (16 * C_ROW) + ks * 32);
#pragma unroll
            for (int p = 0; p < 4; p++) {
                uint32_t bh4[4], bl4[4];
                ldsm_x4(bh4, bB + ST_BH + p * (16 * C_ROW) + ks * 32);
                ldsm_x4(bl4, bB + ST_BL + p * (16 * C_ROW) + ks * 32);
#pragma unroll
                for (int mf = 0; mf < 2; mf++)
#pragma unroll
                    for (int h = 0; h < 2; h++) {
                        float* a4 = acc[mf][2 * p + h];
                        mma_fp16(a4, ahf[mf], &bh4[h * 2]);
                        mma_fp16(a4, ahf[mf], &bl4[h * 2]);
                    }
            }
        }
        __syncthreads();
    }

    // epilogue -> fp16
#pragma unroll
    for (int mf = 0; mf < 2; mf++) {
        int r0 = rowBase + wm * 32 + mf * 16 + (lane >> 2);
#pragma unroll
        for (int nf = 0; nf < 8; nf++) {
            int col = wn * 64 + nf * 8 + 2 * (lane & 3);
            if (r0 < M)
                *(__half2*)(g_Wh_h + (size_t)r0 * OUT_F + col) =
                    __floats2half2_rn(acc[mf][nf][0], acc[mf][nf][1]);
            if (r0 + 8 < M)
                *(__half2*)(g_Wh_h + (size_t)(r0 + 8) * OUT_F + col) =
                    __floats2half2_rn(acc[mf][nf][2], acc[mf][nf][3]);
        }
    }
}

// ---------------------------------------------------------------------------
// Kernel 2: degree histogram over src   (adj is INT32: [2, E] row-major)
// ---------------------------------------------------------------------------
__global__ void k_count(const int* __restrict__ adj, int E) {
    int e = blockIdx.x * blockDim.x + threadIdx.x;
    if (e < E) atomicAdd(&g_deg[adj[e]], 1);
}

// ---------------------------------------------------------------------------
// Kernels 3-5: exclusive scan of g_deg -> g_rowstart (and g_cursor copy)
// ---------------------------------------------------------------------------
__global__ void k_scan1(int n) {
    __shared__ int sm[SCAN_BLK];
    int i = blockIdx.x * SCAN_BLK + threadIdx.x;
    int v = (i < n) ? g_deg[i] : 0;
    sm[threadIdx.x] = v;
    __syncthreads();
    for (int off = 1; off < SCAN_BLK; off <<= 1) {
        int add = (threadIdx.x >= off) ? sm[threadIdx.x - off] : 0;
        __syncthreads();
        sm[threadIdx.x] += add;
        __syncthreads();
    }
    if (i < n) g_rowstart[i] = sm[threadIdx.x] - v;
    if (threadIdx.x == SCAN_BLK - 1) g_bsum[blockIdx.x] = sm[SCAN_BLK - 1];
}

__global__ void k_scan2(int nb) {
    __shared__ int sm[256];
    int t = threadIdx.x;
    int v = (t < nb) ? g_bsum[t] : 0;
    sm[t] = v;
    __syncthreads();
    for (int off = 1; off < 256; off <<= 1) {
        int add = (t >= off) ? sm[t - off] : 0;
        __syncthreads();
        sm[t] += add;
        __syncthreads();
    }
    if (t < nb) g_bsum[t] = sm[t] - v;
}

__global__ void k_scan3(int n) {
    int i = blockIdx.x * blockDim.x + threadIdx.x;
    if (i < n) {
        int rs = g_rowstart[i] + g_bsum[i >> 9];
        g_rowstart[i] = rs;
        g_cursor[i]   = rs;
    }
}

// ---------------------------------------------------------------------------
// Kernel 6: scatter edges into CSR (dst per slot)
// ---------------------------------------------------------------------------
__global__ void k_scatter(const int* __restrict__ adj, int E) {
    int e = blockIdx.x * blockDim.x + threadIdx.x;
    if (e < E) {
        int s = adj[e];
        int d = adj[E + e];
        int p = atomicAdd(&g_cursor[s], 1);
        g_edst[p] = d;
    }
}

// ---------------------------------------------------------------------------
// Kernel 7a: warp-per-node attention -> normalized weights in g_att
// ---------------------------------------------------------------------------
__global__ __launch_bounds__(256) void k_attention(
    const float* __restrict__ label,   // [N, 32]
    int n)
{
    const int wl   = threadIdx.x >> 5;
    const int lane = threadIdx.x & 31;
    const int w    = blockIdx.x * 8 + wl;
    if (w >= n) return;

    const float labi = label[(size_t)w * D_LABEL + lane];
    const int start = g_rowstart[w];
    const int d     = g_deg[w];

    float denom = 0.0f;
    int k = 0;
    for (; k + 1 < d; k += 2) {
        int j0 = __ldg(g_edst + start + k);
        int j1 = __ldg(g_edst + start + k + 1);
        float v0 = labi * __ldg(label + (size_t)j0 * D_LABEL + lane);
        float v1 = labi * __ldg(label + (size_t)j1 * D_LABEL + lane);
#pragma unroll
        for (int o = 16; o > 0; o >>= 1) {
            v0 += __shfl_xor_sync(0xffffffffu, v0, o);
            v1 += __shfl_xor_sync(0xffffffffu, v1, o);
        }
        float e0 = (v0 >= 0.0f) ? v0 : ALPHA * v0;
        float e1 = (v1 >= 0.0f) ? v1 : ALPHA * v1;
        float ex0 = __expf(e0);
        float ex1 = __expf(e1);
        denom += ex0 + ex1;
        if (lane == (k & 31))       g_att[start + k]     = ex0;
        if (lane == ((k + 1) & 31)) g_att[start + k + 1] = ex1;
    }
    if (k < d) {
        int j0 = __ldg(g_edst + start + k);
        float v0 = labi * __ldg(label + (size_t)j0 * D_LABEL + lane);
#pragma unroll
        for (int o = 16; o > 0; o >>= 1)
            v0 += __shfl_xor_sync(0xffffffffu, v0, o);
        float e0 = (v0 >= 0.0f) ? v0 : ALPHA * v0;
        float ex0 = __expf(e0);
        denom += ex0;
        if (lane == (k & 31)) g_att[start + k] = ex0;
    }
    const float inv = 1.0f / fmaxf(denom, EPS_RS);
    for (int t = lane; t < d; t += 32)
        g_att[start + t] *= inv;
}

// ---------------------------------------------------------------------------
// Kernel 7b: gather — exact R7 form (proven best)
// 1 warp per node; lane covers 8 cols (uint4 of fp16); 4 edges in flight
// ---------------------------------------------------------------------------
__device__ __forceinline__ void fma8_h(float* acc, uint4 v, float a) {
    float2 f;
    f = __half22float2(*(__half2*)&v.x);
    acc[0] = fmaf(a, f.x, acc[0]); acc[1] = fmaf(a, f.y, acc[1]);
    f = __half22float2(*((__half2*)&v.x + 1));
    acc[2] = fmaf(a, f.x, acc[2]); acc[3] = fmaf(a, f.y, acc[3]);
    f = __half22float2(*(__half2*)&v.z);
    acc[4] = fmaf(a, f.x, acc[4]); acc[5] = fmaf(a, f.y, acc[5]);
    f = __half22float2(*((__half2*)&v.z + 1));
    acc[6] = fmaf(a, f.x, acc[6]); acc[7] = fmaf(a, f.y, acc[7]);
}

__global__ __launch_bounds__(256) void k_gather(
    float* __restrict__ out,   // [N, 256]
    int n)
{
    const int w    = blockIdx.x * 8 + (threadIdx.x >> 5);
    const int lane = threadIdx.x & 31;
    if (w >= n) return;

    const int start = g_rowstart[w];
    const int d     = g_deg[w];
    const __half* base = g_Wh_h + lane * 8;   // 16B per lane, 512B per warp row

    float acc[8];
#pragma unroll
    for (int q = 0; q < 8; q++) acc[q] = 0.0f;

    int k = 0;
    for (; k + 3 < d; k += 4) {
        int j0 = __ldg(g_edst + start + k);
        int j1 = __ldg(g_edst + start + k + 1);
        int j2 = __ldg(g_edst + start + k + 2);
        int j3 = __ldg(g_edst + start + k + 3);
        float a0 = __ldg(g_att + start + k);
        float a1 = __ldg(g_att + start + k + 1);
        float a2 = __ldg(g_att + start + k + 2);
        float a3 = __ldg(g_att + start + k + 3);
        uint4 v0 = __ldg((const uint4*)(base + (size_t)j0 * OUT_F));
        uint4 v1 = __ldg((const uint4*)(base + (size_t)j1 * OUT_F));
        uint4 v2 = __ldg((const uint4*)(base + (size_t)j2 * OUT_F));
        uint4 v3 = __ldg((const uint4*)(base + (size_t)j3 * OUT_F));
        fma8_h(acc, v0, a0);
        fma8_h(acc, v1, a1);
        fma8_h(acc, v2, a2);
        fma8_h(acc, v3, a3);
    }
    for (; k < d; k++) {
        int j0 = __ldg(g_edst + start + k);
        float a0 = __ldg(g_att + start + k);
        uint4 v0 = __ldg((const uint4*)(base + (size_t)j0 * OUT_F));
        fma8_h(acc, v0, a0);
    }

    float* o = out + (size_t)w * OUT_F + lane * 8;
    *(float4*)(o + 0) = make_float4(acc[0], acc[1], acc[2], acc[3]);
    *(float4*)(o + 4) = make_float4(acc[4], acc[5], acc[6], acc[7]);
}

// ---------------------------------------------------------------------------
// Launch — stream fork: branch A = prep_W + GEMM (default stream),
//                        branch B = CSR build + attention (s2), join -> gather
// ---------------------------------------------------------------------------
extern "C" void kernel_launch(void* const* d_in, const int* in_sizes, int n_in,
                              void* d_out, int out_size)
{
    const float* h     = (const float*)d_in[0];   // [N, 256] fp32
    const float* label = (const float*)d_in[1];   // [N, 32]  fp32
    const float* W     = (const float*)d_in[2];   // [256, 256] fp32
    const int*   adj   = (const int*)d_in[3];     // [2, E] int32
    float*       out   = (float*)d_out;

    const int N = in_sizes[0] / IN_F;      // 100000
    const int E = in_sizes[3] / 2;         // 1600000

    const int T = 256;
    const int gbN = (N + T - 1) / T;
    const int gbE = (E + T - 1) / T;

    static cudaStream_t s2 = nullptr;
    static cudaEvent_t  evF = nullptr, evJ = nullptr;
    if (s2 == nullptr) {
        cudaFuncSetAttribute(k_gemm_mma, cudaFuncAttributeMaxDynamicSharedMemorySize, GSM_TOTAL);
        cudaStreamCreateWithFlags(&s2, cudaStreamNonBlocking);
        cudaEventCreateWithFlags(&evF, cudaEventDisableTiming);
        cudaEventCreateWithFlags(&evJ, cudaEventDisableTiming);
    }

    // fork
    cudaEventRecord(evF, 0);
    cudaStreamWaitEvent(s2, evF, 0);

    // ---- branch B (s2): CSR build + attention weights
    k_zero_deg<<<gbN, T, 0, s2>>>(N);
    k_count<<<gbE, T, 0, s2>>>(adj, E);
    int nb = (N + SCAN_BLK - 1) / SCAN_BLK;
    k_scan1<<<nb, SCAN_BLK, 0, s2>>>(N);
    k_scan2<<<1, 256, 0, s2>>>(nb);
    k_scan3<<<gbN, T, 0, s2>>>(N);
    k_scatter<<<gbE, T, 0, s2>>>(adj, E);
    k_attention<<<(N + 7) / 8, 256, 0, s2>>>(label, N);
    cudaEventRecord(evJ, s2);

    // ---- branch A (default stream): GEMM (full-N CTA, A read once, fp16 2-product)
    k_prep_W<<<256, 256>>>(W);
    dim3 ggrid(1, (N + 127) / 128);
    k_gemm_mma<<<ggrid, 512, GSM_TOTAL>>>(h, N);

    // join, then gather
    cudaStreamWaitEvent(0, evJ, 0);
    k_gather<<<(N + 7) / 8, 256>>>(out, N);
}

// round 13
// speedup vs baseline: 1.4444x; 1.1182x over previous
#include <cuda_runtime.h>
#include <cuda_bf16.h>
#include <cuda_fp16.h>
#include <math.h>
#include <stdint.h>

// Problem constants (fixed by the dataset)
#define N_NODES   100000
#define N_EDGES   1600000
#define IN_F      256
#define OUT_F     256
#define D_LABEL   32
#define ALPHA     0.2f
#define EPS_RS    1e-9f

#define SCAN_BLK  512

// Scratch (device globals: allowed; no cudaMalloc anywhere)
__device__ __half g_Wh_h[(size_t)N_NODES * OUT_F];   // ~50 MB (fp16 Wh)
__device__ float g_att[N_EDGES];
__device__ int   g_deg[N_NODES];
__device__ int   g_rowstart[N_NODES];
__device__ int   g_cursor[N_NODES];
__device__ int   g_edst[N_EDGES];
__device__ int   g_bsum[256];
// W transposed, fp16: Wt[n][k] = W[k][n]
__device__ __half g_Wt16[256 * 256];

// ---------------------------------------------------------------------------
// helpers
// ---------------------------------------------------------------------------
__device__ __forceinline__ uint32_t smem_u32(const void* p) {
    uint32_t a;
    asm("{ .reg .u64 t; cvta.to.shared.u64 t, %1; cvt.u32.u64 %0, t; }"
        : "=r"(a) : "l"(p));
    return a;
}

__device__ __forceinline__ void ldsm_x4(uint32_t* r, uint32_t addr) {
    asm volatile("ldmatrix.sync.aligned.m8n8.x4.shared.b16 {%0,%1,%2,%3}, [%4];"
                 : "=r"(r[0]), "=r"(r[1]), "=r"(r[2]), "=r"(r[3]) : "r"(addr));
}
__device__ __forceinline__ void mma_fp16(float* c, const uint32_t* a, const uint32_t* b) {
    asm volatile(
        "mma.sync.aligned.m16n8k16.row.col.f32.f16.f16.f32 "
        "{%0,%1,%2,%3}, {%4,%5,%6,%7}, {%8,%9}, {%0,%1,%2,%3};"
        : "+f"(c[0]), "+f"(c[1]), "+f"(c[2]), "+f"(c[3])
        : "r"(a[0]), "r"(a[1]), "r"(a[2]), "r"(a[3]), "r"(b[0]), "r"(b[1]));
}

// ---------------------------------------------------------------------------
// Kernel 0: zero degree array
// ---------------------------------------------------------------------------
__global__ void k_zero_deg(int n) {
    int i = blockIdx.x * blockDim.x + threadIdx.x;
    if (i < n) g_deg[i] = 0;
}

// ---------------------------------------------------------------------------
// Kernel P: W [K,N] fp32 -> Wt16 [N,K] fp16
// ---------------------------------------------------------------------------
__global__ void k_prep_W(const float* __restrict__ W) {
    int i = blockIdx.x * 256 + threadIdx.x;     // 0..65535
    int n = i >> 8, k = i & 255;
    g_Wt16[n * 256 + k] = __float2half_rn(W[k * 256 + n]);
}

// ---------------------------------------------------------------------------
// Kernel 1: HMMA GEMM  Wh = h @ W, pure fp16 operands (1 product), fp32 accum.
// CTA 128M x 256N, 512 threads (warp grid 4x4, warp tile 32x64), A read once,
// both operands chunk-staged (K chunks of 32), double-buffered. smem 60KB.
// ---------------------------------------------------------------------------
#define C_ROW 80
#define ST_A  0                    // A 128*80 = 10240
#define ST_B  10240                // B 256*80 = 20480
#define STAGE_SZ 30720
#define GSM_TOTAL (2 * STAGE_SZ)   // 61440

__global__ __launch_bounds__(512, 1) void k_gemm_mma(const float* __restrict__ A, int M)
{
    extern __shared__ __align__(16) char sm[];
    const uint32_t sbase = smem_u32(sm);
    const int tid  = threadIdx.x;
    const int lane = tid & 31;
    const int wid  = tid >> 5;          // 0..15
    const int wm   = wid >> 2;          // 0..3
    const int wn   = wid & 3;           // 0..3
    const int rowBase = blockIdx.y * 128;

    float acc[2][8][4];
#pragma unroll
    for (int i = 0; i < 2; i++)
#pragma unroll
        for (int j = 0; j < 8; j++)
#pragma unroll
            for (int q = 0; q < 4; q++) acc[i][j][q] = 0.0f;

    // ---- A fill mapping: thread -> (row, quarter of 32-float chunk)
    const int ar = tid >> 2;            // 0..127
    const int aq = tid & 3;             // 0..3 (8 floats -> 8 fp16 = 16B)
    const int grow = rowBase + ar;
    const float* aptr = A + (size_t)grow * IN_F + aq * 8;

    // ---- B fill mapping: 2 slots per thread: i = tid, tid+512 -> (n, q)
    const int bn0 = tid >> 2;           // 0..127
    const int bn1 = (tid + 512) >> 2;   // 128..255
    const int bq  = tid & 3;

    // prefetch chunk 0
    float4 pfA0 = make_float4(0.f,0.f,0.f,0.f), pfA1 = pfA0;
    if (grow < M) {
        pfA0 = *(const float4*)(aptr + 0);
        pfA1 = *(const float4*)(aptr + 4);
    }
    uint4 pfB0 = *(const uint4*)((const char*)g_Wt16 + (size_t)bn0 * 512 + bq * 16);
    uint4 pfB1 = *(const uint4*)((const char*)g_Wt16 + (size_t)bn1 * 512 + bq * 16);

    // fragment address bases
    const uint32_t a_frag_off = (uint32_t)((wm * 32 + (lane & 15)) * C_ROW + (lane >> 4) * 16);
    const uint32_t b4_frag_off = (uint32_t)(
        (wn * 64 + (lane & 7) + ((lane >> 4) & 1) * 8) * C_ROW + ((lane >> 3) & 1) * 16);
    const uint32_t a_sts = (uint32_t)(ar * C_ROW + aq * 16);
    const uint32_t b_sts0 = (uint32_t)(bn0 * C_ROW + bq * 16);
    const uint32_t b_sts1 = (uint32_t)(bn1 * C_ROW + bq * 16);

    for (int c = 0; c < 8; c++) {
        const int stage = c & 1;
        char* stg = sm + stage * STAGE_SZ;
        // ---- store A (convert fp32 -> fp16)
        {
            __half2 p0 = __floats2half2_rn(pfA0.x, pfA0.y);
            __half2 p1 = __floats2half2_rn(pfA0.z, pfA0.w);
            __half2 p2 = __floats2half2_rn(pfA1.x, pfA1.y);
            __half2 p3 = __floats2half2_rn(pfA1.z, pfA1.w);
            uint4 v;
            v.x = *(uint32_t*)&p0; v.y = *(uint32_t*)&p1;
            v.z = *(uint32_t*)&p2; v.w = *(uint32_t*)&p3;
            *(uint4*)(stg + ST_A + a_sts) = v;
        }
        // ---- store B (already fp16)
        *(uint4*)(stg + ST_B + b_sts0) = pfB0;
        *(uint4*)(stg + ST_B + b_sts1) = pfB1;
        __syncthreads();

        // ---- prefetch next chunk
        if (c < 7) {
            if (grow < M) {
                pfA0 = *(const float4*)(aptr + (c + 1) * 32 + 0);
                pfA1 = *(const float4*)(aptr + (c + 1) * 32 + 4);
            }
            pfB0 = *(const uint4*)((const char*)g_Wt16 + (size_t)bn0 * 512 + (c + 1) * 64 + bq * 16);
            pfB1 = *(const uint4*)((const char*)g_Wt16 + (size_t)bn1 * 512 + (c + 1) * 64 + bq * 16);
        }

        // ---- compute chunk
        const uint32_t aB = sbase + stage * STAGE_SZ + a_frag_off;
        const uint32_t bB = sbase + stage * STAGE_SZ + b4_frag_off;
#pragma unroll
        for (int ks = 0; ks < 2; ks++) {
            uint32_t ahf[2][4];
#pragma unroll
            for (int mf = 0; mf < 2; mf++)
                ldsm_x4(ahf[mf], aB + ST_A + mf * (16 * C_ROW) + ks * 32);
#pragma unroll
            for (int p = 0; p < 4; p++) {
                uint32_t b4[4];
                ldsm_x4(b4, bB + ST_B + p * (16 * C_ROW) + ks * 32);
#pragma unroll
                for (int mf = 0; mf < 2; mf++)
#pragma unroll
                    for (int h = 0; h < 2; h++)
                        mma_fp16(acc[mf][2 * p + h], ahf[mf], &b4[h * 2]);
            }
        }
        __syncthreads();
    }

    // epilogue -> fp16
#pragma unroll
    for (int mf = 0; mf < 2; mf++) {
        int r0 = rowBase + wm * 32 + mf * 16 + (lane >> 2);
#pragma unroll
        for (int nf = 0; nf < 8; nf++) {
            int col = wn * 64 + nf * 8 + 2 * (lane & 3);
            if (r0 < M)
                *(__half2*)(g_Wh_h + (size_t)r0 * OUT_F + col) =
                    __floats2half2_rn(acc[mf][nf][0], acc[mf][nf][1]);
            if (r0 + 8 < M)
                *(__half2*)(g_Wh_h + (size_t)(r0 + 8) * OUT_F + col) =
                    __floats2half2_rn(acc[mf][nf][2], acc[mf][nf][3]);
        }
    }
}

// ---------------------------------------------------------------------------
// Kernel 2: degree histogram over src   (adj is INT32: [2, E] row-major)
// ---------------------------------------------------------------------------
__global__ void k_count(const int* __restrict__ adj, int E) {
    int e = blockIdx.x * blockDim.x + threadIdx.x;
    if (e < E) atomicAdd(&g_deg[adj[e]], 1);
}

// ---------------------------------------------------------------------------
// Kernels 3-5: exclusive scan of g_deg -> g_rowstart (and g_cursor copy)
// ---------------------------------------------------------------------------
__global__ void k_scan1(int n) {
    __shared__ int sm[SCAN_BLK];
    int i = blockIdx.x * SCAN_BLK + threadIdx.x;
    int v = (i < n) ? g_deg[i] : 0;
    sm[threadIdx.x] = v;
    __syncthreads();
    for (int off = 1; off < SCAN_BLK; off <<= 1) {
        int add = (threadIdx.x >= off) ? sm[threadIdx.x - off] : 0;
        __syncthreads();
        sm[threadIdx.x] += add;
        __syncthreads();
    }
    if (i < n) g_rowstart[i] = sm[threadIdx.x] - v;
    if (threadIdx.x == SCAN_BLK - 1) g_bsum[blockIdx.x] = sm[SCAN_BLK - 1];
}

__global__ void k_scan2(int nb) {
    __shared__ int sm[256];
    int t = threadIdx.x;
    int v = (t < nb) ? g_bsum[t] : 0;
    sm[t] = v;
    __syncthreads();
    for (int off = 1; off < 256; off <<= 1) {
        int add = (t >= off) ? sm[t - off] : 0;
        __syncthreads();
        sm[t] += add;
        __syncthreads();
    }
    if (t < nb) g_bsum[t] = sm[t] - v;
}

__global__ void k_scan3(int n) {
    int i = blockIdx.x * blockDim.x + threadIdx.x;
    if (i < n) {
        int rs = g_rowstart[i] + g_bsum[i >> 9];
        g_rowstart[i] = rs;
        g_cursor[i]   = rs;
    }
}

// ---------------------------------------------------------------------------
// Kernel 6: scatter edges into CSR (dst per slot)
// ---------------------------------------------------------------------------
__global__ void k_scatter(const int* __restrict__ adj, int E) {
    int e = blockIdx.x * blockDim.x + threadIdx.x;
    if (e < E) {
        int s = adj[e];
        int d = adj[E + e];
        int p = atomicAdd(&g_cursor[s], 1);
        g_edst[p] = d;
    }
}

// ---------------------------------------------------------------------------
// Kernel 7a: warp-per-node attention -> normalized weights in g_att
// ---------------------------------------------------------------------------
__global__ __launch_bounds__(256) void k_attention(
    const float* __restrict__ label,   // [N, 32]
    int n)
{
    const int wl   = threadIdx.x >> 5;
    const int lane = threadIdx.x & 31;
    const int w    = blockIdx.x * 8 + wl;
    if (w >= n) return;

    const float labi = label[(size_t)w * D_LABEL + lane];
    const int start = g_rowstart[w];
    const int d     = g_deg[w];

    float denom = 0.0f;
    int k = 0;
    for (; k + 1 < d; k += 2) {
        int j0 = __ldg(g_edst + start + k);
        int j1 = __ldg(g_edst + start + k + 1);
        float v0 = labi * __ldg(label + (size_t)j0 * D_LABEL + lane);
        float v1 = labi * __ldg(label + (size_t)j1 * D_LABEL + lane);
#pragma unroll
        for (int o = 16; o > 0; o >>= 1) {
            v0 += __shfl_xor_sync(0xffffffffu, v0, o);
            v1 += __shfl_xor_sync(0xffffffffu, v1, o);
        }
        float e0 = (v0 >= 0.0f) ? v0 : ALPHA * v0;
        float e1 = (v1 >= 0.0f) ? v1 : ALPHA * v1;
        float ex0 = __expf(e0);
        float ex1 = __expf(e1);
        denom += ex0 + ex1;
        if (lane == (k & 31))       g_att[start + k]     = ex0;
        if (lane == ((k + 1) & 31)) g_att[start + k + 1] = ex1;
    }
    if (k < d) {
        int j0 = __ldg(g_edst + start + k);
        float v0 = labi * __ldg(label + (size_t)j0 * D_LABEL + lane);
#pragma unroll
        for (int o = 16; o > 0; o >>= 1)
            v0 += __shfl_xor_sync(0xffffffffu, v0, o);
        float e0 = (v0 >= 0.0f) ? v0 : ALPHA * v0;
        float ex0 = __expf(e0);
        denom += ex0;
        if (lane == (k & 31)) g_att[start + k] = ex0;
    }
    const float inv = 1.0f / fmaxf(denom, EPS_RS);
    for (int t = lane; t < d; t += 32)
        g_att[start + t] *= inv;
}

// ---------------------------------------------------------------------------
// Kernel 7b: gather — R7 loop structure + __stcs output (evict-first, keeps
// Wh resident in L2 against the 100MB output stream)
// ---------------------------------------------------------------------------
__device__ __forceinline__ void fma8_h(float* acc, uint4 v, float a) {
    float2 f;
    f = __half22float2(*(__half2*)&v.x);
    acc[0] = fmaf(a, f.x, acc[0]); acc[1] = fmaf(a, f.y, acc[1]);
    f = __half22float2(*((__half2*)&v.x + 1));
    acc[2] = fmaf(a, f.x, acc[2]); acc[3] = fmaf(a, f.y, acc[3]);
    f = __half22float2(*(__half2*)&v.z);
    acc[4] = fmaf(a, f.x, acc[4]); acc[5] = fmaf(a, f.y, acc[5]);
    f = __half22float2(*((__half2*)&v.z + 1));
    acc[6] = fmaf(a, f.x, acc[6]); acc[7] = fmaf(a, f.y, acc[7]);
}

__global__ __launch_bounds__(256) void k_gather(
    float* __restrict__ out,   // [N, 256]
    int n)
{
    const int w    = blockIdx.x * 8 + (threadIdx.x >> 5);
    const int lane = threadIdx.x & 31;
    if (w >= n) return;

    const int start = g_rowstart[w];
    const int d     = g_deg[w];
    const __half* base = g_Wh_h + lane * 8;   // 16B per lane, 512B per warp row

    float acc[8];
#pragma unroll
    for (int q = 0; q < 8; q++) acc[q] = 0.0f;

    int k = 0;
    for (; k + 3 < d; k += 4) {
        int j0 = __ldg(g_edst + start + k);
        int j1 = __ldg(g_edst + start + k + 1);
        int j2 = __ldg(g_edst + start + k + 2);
        int j3 = __ldg(g_edst + start + k + 3);
        float a0 = __ldg(g_att + start + k);
        float a1 = __ldg(g_att + start + k + 1);
        float a2 = __ldg(g_att + start + k + 2);
        float a3 = __ldg(g_att + start + k + 3);
        uint4 v0 = __ldg((const uint4*)(base + (size_t)j0 * OUT_F));
        uint4 v1 = __ldg((const uint4*)(base + (size_t)j1 * OUT_F));
        uint4 v2 = __ldg((const uint4*)(base + (size_t)j2 * OUT_F));
        uint4 v3 = __ldg((const uint4*)(base + (size_t)j3 * OUT_F));
        fma8_h(acc, v0, a0);
        fma8_h(acc, v1, a1);
        fma8_h(acc, v2, a2);
        fma8_h(acc, v3, a3);
    }
    for (; k < d; k++) {
        int j0 = __ldg(g_edst + start + k);
        float a0 = __ldg(g_att + start + k);
        uint4 v0 = __ldg((const uint4*)(base + (size_t)j0 * OUT_F));
        fma8_h(acc, v0, a0);
    }

    float* o = out + (size_t)w * OUT_F + lane * 8;
    __stcs((float4*)(o + 0), make_float4(acc[0], acc[1], acc[2], acc[3]));
    __stcs((float4*)(o + 4), make_float4(acc[4], acc[5], acc[6], acc[7]));
}

// ---------------------------------------------------------------------------
// Launch — stream fork: branch A = prep_W + GEMM (default stream),
//                        branch B = CSR build + attention (s2), join -> gather
// ---------------------------------------------------------------------------
extern "C" void kernel_launch(void* const* d_in, const int* in_sizes, int n_in,
                              void* d_out, int out_size)
{
    const float* h     = (const float*)d_in[0];   // [N, 256] fp32
    const float* label = (const float*)d_in[1];   // [N, 32]  fp32
    const float* W     = (const float*)d_in[2];   // [256, 256] fp32
    const int*   adj   = (const int*)d_in[3];     // [2, E] int32
    float*       out   = (float*)d_out;

    const int N = in_sizes[0] / IN_F;      // 100000
    const int E = in_sizes[3] / 2;         // 1600000

    const int T = 256;
    const int gbN = (N + T - 1) / T;
    const int gbE = (E + T - 1) / T;

    static cudaStream_t s2 = nullptr;
    static cudaEvent_t  evF = nullptr, evJ = nullptr;
    if (s2 == nullptr) {
        cudaFuncSetAttribute(k_gemm_mma, cudaFuncAttributeMaxDynamicSharedMemorySize, GSM_TOTAL);
        cudaStreamCreateWithFlags(&s2, cudaStreamNonBlocking);
        cudaEventCreateWithFlags(&evF, cudaEventDisableTiming);
        cudaEventCreateWithFlags(&evJ, cudaEventDisableTiming);
    }

    // fork
    cudaEventRecord(evF, 0);
    cudaStreamWaitEvent(s2, evF, 0);

    // ---- branch B (s2): CSR build + attention weights
    k_zero_deg<<<gbN, T, 0, s2>>>(N);
    k_count<<<gbE, T, 0, s2>>>(adj, E);
    int nb = (N + SCAN_BLK - 1) / SCAN_BLK;
    k_scan1<<<nb, SCAN_BLK, 0, s2>>>(N);
    k_scan2<<<1, 256, 0, s2>>>(nb);
    k_scan3<<<gbN, T, 0, s2>>>(N);
    k_scatter<<<gbE, T, 0, s2>>>(adj, E);
    k_attention<<<(N + 7) / 8, 256, 0, s2>>>(label, N);
    cudaEventRecord(evJ, s2);

    // ---- branch A (default stream): GEMM (full-N CTA, A read once, fp16 1-product)
    k_prep_W<<<256, 256>>>(W);
    dim3 ggrid(1, (N + 127) / 128);
    k_gemm_mma<<<ggrid, 512, GSM_TOTAL>>>(h, N);

    // join, then gather
    cudaStreamWaitEvent(0, evJ, 0);
    k_gather<<<(N + 7) / 8, 256>>>(out, N);
}

// round 14
// speedup vs baseline: 1.4562x; 1.0081x over previous
#include <cuda_runtime.h>
#include <cuda_bf16.h>
#include <cuda_fp16.h>
#include <math.h>
#include <stdint.h>

// Problem constants (fixed by the dataset)
#define N_NODES   100000
#define N_EDGES   1600000
#define IN_F      256
#define OUT_F     256
#define D_LABEL   32
#define ALPHA     0.2f
#define EPS_RS    1e-9f

#define SCAN_BLK  512

// Scratch (device globals: allowed; no cudaMalloc anywhere)
__device__ __half g_Wh_h[(size_t)N_NODES * OUT_F];   // ~50 MB (fp16 Wh)
__device__ float g_att[N_EDGES];
__device__ int   g_deg[N_NODES];
__device__ int   g_rowstart[N_NODES];
__device__ int   g_cursor[N_NODES];
__device__ int   g_edst[N_EDGES];
__device__ int   g_bsum[256];
// W transposed, fp16: Wt[n][k] = W[k][n]
__device__ __half g_Wt16[256 * 256];

// ---------------------------------------------------------------------------
// helpers
// ---------------------------------------------------------------------------
__device__ __forceinline__ uint32_t smem_u32(const void* p) {
    uint32_t a;
    asm("{ .reg .u64 t; cvta.to.shared.u64 t, %1; cvt.u32.u64 %0, t; }"
        : "=r"(a) : "l"(p));
    return a;
}

__device__ __forceinline__ void ldsm_x4(uint32_t* r, uint32_t addr) {
    asm volatile("ldmatrix.sync.aligned.m8n8.x4.shared.b16 {%0,%1,%2,%3}, [%4];"
                 : "=r"(r[0]), "=r"(r[1]), "=r"(r[2]), "=r"(r[3]) : "r"(addr));
}
__device__ __forceinline__ void mma_fp16(float* c, const uint32_t* a, const uint32_t* b) {
    asm volatile(
        "mma.sync.aligned.m16n8k16.row.col.f32.f16.f16.f32 "
        "{%0,%1,%2,%3}, {%4,%5,%6,%7}, {%8,%9}, {%0,%1,%2,%3};"
        : "+f"(c[0]), "+f"(c[1]), "+f"(c[2]), "+f"(c[3])
        : "r"(a[0]), "r"(a[1]), "r"(a[2]), "r"(a[3]), "r"(b[0]), "r"(b[1]));
}

// ---------------------------------------------------------------------------
// Kernel 0: zero degree array
// ---------------------------------------------------------------------------
__global__ void k_zero_deg(int n) {
    int i = blockIdx.x * blockDim.x + threadIdx.x;
    if (i < n) g_deg[i] = 0;
}

// ---------------------------------------------------------------------------
// Kernel P: W [K,N] fp32 -> Wt16 [N,K] fp16
// ---------------------------------------------------------------------------
__global__ void k_prep_W(const float* __restrict__ W) {
    int i = blockIdx.x * 256 + threadIdx.x;     // 0..65535
    int n = i >> 8, k = i & 255;
    g_Wt16[n * 256 + k] = __float2half_rn(W[k * 256 + n]);
}

// ---------------------------------------------------------------------------
// Kernel 1: HMMA GEMM  Wh = h @ W, pure fp16 operands (1 product), fp32 accum.
// CTA 128M x 256N, 512 threads (warp grid 4x4, warp tile 32x64), A read once,
// both operands chunk-staged (K chunks of 32), double-buffered. smem 60KB.
// ---------------------------------------------------------------------------
#define C_ROW 80
#define ST_A  0                    // A 128*80 = 10240
#define ST_B  10240                // B 256*80 = 20480
#define STAGE_SZ 30720
#define GSM_TOTAL (2 * STAGE_SZ)   // 61440

__global__ __launch_bounds__(512, 1) void k_gemm_mma(const float* __restrict__ A, int M)
{
    extern __shared__ __align__(16) char sm[];
    const uint32_t sbase = smem_u32(sm);
    const int tid  = threadIdx.x;
    const int lane = tid & 31;
    const int wid  = tid >> 5;          // 0..15
    const int wm   = wid >> 2;          // 0..3
    const int wn   = wid & 3;           // 0..3
    const int rowBase = blockIdx.y * 128;

    float acc[2][8][4];
#pragma unroll
    for (int i = 0; i < 2; i++)
#pragma unroll
        for (int j = 0; j < 8; j++)
#pragma unroll
            for (int q = 0; q < 4; q++) acc[i][j][q] = 0.0f;

    const int ar = tid >> 2;            // 0..127
    const int aq = tid & 3;             // 0..3 (8 floats -> 8 fp16 = 16B)
    const int grow = rowBase + ar;
    const float* aptr = A + (size_t)grow * IN_F + aq * 8;

    const int bn0 = tid >> 2;           // 0..127
    const int bn1 = (tid + 512) >> 2;   // 128..255
    const int bq  = tid & 3;

    float4 pfA0 = make_float4(0.f,0.f,0.f,0.f), pfA1 = pfA0;
    if (grow < M) {
        pfA0 = *(const float4*)(aptr + 0);
        pfA1 = *(const float4*)(aptr + 4);
    }
    uint4 pfB0 = *(const uint4*)((const char*)g_Wt16 + (size_t)bn0 * 512 + bq * 16);
    uint4 pfB1 = *(const uint4*)((const char*)g_Wt16 + (size_t)bn1 * 512 + bq * 16);

    const uint32_t a_frag_off = (uint32_t)((wm * 32 + (lane & 15)) * C_ROW + (lane >> 4) * 16);
    const uint32_t b4_frag_off = (uint32_t)(
        (wn * 64 + (lane & 7) + ((lane >> 4) & 1) * 8) * C_ROW + ((lane >> 3) & 1) * 16);
    const uint32_t a_sts = (uint32_t)(ar * C_ROW + aq * 16);
    const uint32_t b_sts0 = (uint32_t)(bn0 * C_ROW + bq * 16);
    const uint32_t b_sts1 = (uint32_t)(bn1 * C_ROW + bq * 16);

    for (int c = 0; c < 8; c++) {
        const int stage = c & 1;
        char* stg = sm + stage * STAGE_SZ;
        {
            __half2 p0 = __floats2half2_rn(pfA0.x, pfA0.y);
            __half2 p1 = __floats2half2_rn(pfA0.z, pfA0.w);
            __half2 p2 = __floats2half2_rn(pfA1.x, pfA1.y);
            __half2 p3 = __floats2half2_rn(pfA1.z, pfA1.w);
            uint4 v;
            v.x = *(uint32_t*)&p0; v.y = *(uint32_t*)&p1;
            v.z = *(uint32_t*)&p2; v.w = *(uint32_t*)&p3;
            *(uint4*)(stg + ST_A + a_sts) = v;
        }
        *(uint4*)(stg + ST_B + b_sts0) = pfB0;
        *(uint4*)(stg + ST_B + b_sts1) = pfB1;
        __syncthreads();

        if (c < 7) {
            if (grow < M) {
                pfA0 = *(const float4*)(aptr + (c + 1) * 32 + 0);
                pfA1 = *(const float4*)(aptr + (c + 1) * 32 + 4);
            }
            pfB0 = *(const uint4*)((const char*)g_Wt16 + (size_t)bn0 * 512 + (c + 1) * 64 + bq * 16);
            pfB1 = *(const uint4*)((const char*)g_Wt16 + (size_t)bn1 * 512 + (c + 1) * 64 + bq * 16);
        }

        const uint32_t aB = sbase + stage * STAGE_SZ + a_frag_off;
        const uint32_t bB = sbase + stage * STAGE_SZ + b4_frag_off;
#pragma unroll
        for (int ks = 0; ks < 2; ks++) {
            uint32_t ahf[2][4];
#pragma unroll
            for (int mf = 0; mf < 2; mf++)
                ldsm_x4(ahf[mf], aB + ST_A + mf * (16 * C_ROW) + ks * 32);
#pragma unroll
            for (int p = 0; p < 4; p++) {
                uint32_t b4[4];
                ldsm_x4(b4, bB + ST_B + p * (16 * C_ROW) + ks * 32);
#pragma unroll
                for (int mf = 0; mf < 2; mf++)
#pragma unroll
                    for (int h = 0; h < 2; h++)
                        mma_fp16(acc[mf][2 * p + h], ahf[mf], &b4[h * 2]);
            }
        }
        __syncthreads();
    }

    // epilogue -> fp16
#pragma unroll
    for (int mf = 0; mf < 2; mf++) {
        int r0 = rowBase + wm * 32 + mf * 16 + (lane >> 2);
#pragma unroll
        for (int nf = 0; nf < 8; nf++) {
            int col = wn * 64 + nf * 8 + 2 * (lane & 3);
            if (r0 < M)
                *(__half2*)(g_Wh_h + (size_t)r0 * OUT_F + col) =
                    __floats2half2_rn(acc[mf][nf][0], acc[mf][nf][1]);
            if (r0 + 8 < M)
                *(__half2*)(g_Wh_h + (size_t)(r0 + 8) * OUT_F + col) =
                    __floats2half2_rn(acc[mf][nf][2], acc[mf][nf][3]);
        }
    }
}

// ---------------------------------------------------------------------------
// Kernel 2: degree histogram over src   (adj is INT32: [2, E] row-major)
// ---------------------------------------------------------------------------
__global__ void k_count(const int* __restrict__ adj, int E) {
    int e = blockIdx.x * blockDim.x + threadIdx.x;
    if (e < E) atomicAdd(&g_deg[adj[e]], 1);
}

// ---------------------------------------------------------------------------
// Kernels 3-5: exclusive scan of g_deg -> g_rowstart (and g_cursor copy)
// ---------------------------------------------------------------------------
__global__ void k_scan1(int n) {
    __shared__ int sm[SCAN_BLK];
    int i = blockIdx.x * SCAN_BLK + threadIdx.x;
    int v = (i < n) ? g_deg[i] : 0;
    sm[threadIdx.x] = v;
    __syncthreads();
    for (int off = 1; off < SCAN_BLK; off <<= 1) {
        int add = (threadIdx.x >= off) ? sm[threadIdx.x - off] : 0;
        __syncthreads();
        sm[threadIdx.x] += add;
        __syncthreads();
    }
    if (i < n) g_rowstart[i] = sm[threadIdx.x] - v;
    if (threadIdx.x == SCAN_BLK - 1) g_bsum[blockIdx.x] = sm[SCAN_BLK - 1];
}

__global__ void k_scan2(int nb) {
    __shared__ int sm[256];
    int t = threadIdx.x;
    int v = (t < nb) ? g_bsum[t] : 0;
    sm[t] = v;
    __syncthreads();
    for (int off = 1; off < 256; off <<= 1) {
        int add = (t >= off) ? sm[t - off] : 0;
        __syncthreads();
        sm[t] += add;
        __syncthreads();
    }
    if (t < nb) g_bsum[t] = sm[t] - v;
}

__global__ void k_scan3(int n) {
    int i = blockIdx.x * blockDim.x + threadIdx.x;
    if (i < n) {
        int rs = g_rowstart[i] + g_bsum[i >> 9];
        g_rowstart[i] = rs;
        g_cursor[i]   = rs;
    }
}

// ---------------------------------------------------------------------------
// Kernel 6: scatter edges into CSR (dst per slot)
// ---------------------------------------------------------------------------
__global__ void k_scatter(const int* __restrict__ adj, int E) {
    int e = blockIdx.x * blockDim.x + threadIdx.x;
    if (e < E) {
        int s = adj[e];
        int d = adj[E + e];
        int p = atomicAdd(&g_cursor[s], 1);
        g_edst[p] = d;
    }
}

// ---------------------------------------------------------------------------
// Kernel 7a: warp-per-node attention -> normalized weights in g_att
// ---------------------------------------------------------------------------
__global__ __launch_bounds__(256) void k_attention(
    const float* __restrict__ label,   // [N, 32]
    int n)
{
    const int wl   = threadIdx.x >> 5;
    const int lane = threadIdx.x & 31;
    const int w    = blockIdx.x * 8 + wl;
    if (w >= n) return;

    const float labi = label[(size_t)w * D_LABEL + lane];
    const int start = g_rowstart[w];
    const int d     = g_deg[w];

    float denom = 0.0f;
    int k = 0;
    for (; k + 1 < d; k += 2) {
        int j0 = __ldg(g_edst + start + k);
        int j1 = __ldg(g_edst + start + k + 1);
        float v0 = labi * __ldg(label + (size_t)j0 * D_LABEL + lane);
        float v1 = labi * __ldg(label + (size_t)j1 * D_LABEL + lane);
#pragma unroll
        for (int o = 16; o > 0; o >>= 1) {
            v0 += __shfl_xor_sync(0xffffffffu, v0, o);
            v1 += __shfl_xor_sync(0xffffffffu, v1, o);
        }
        float e0 = (v0 >= 0.0f) ? v0 : ALPHA * v0;
        float e1 = (v1 >= 0.0f) ? v1 : ALPHA * v1;
        float ex0 = __expf(e0);
        float ex1 = __expf(e1);
        denom += ex0 + ex1;
        if (lane == (k & 31))       g_att[start + k]     = ex0;
        if (lane == ((k + 1) & 31)) g_att[start + k + 1] = ex1;
    }
    if (k < d) {
        int j0 = __ldg(g_edst + start + k);
        float v0 = labi * __ldg(label + (size_t)j0 * D_LABEL + lane);
#pragma unroll
        for (int o = 16; o > 0; o >>= 1)
            v0 += __shfl_xor_sync(0xffffffffu, v0, o);
        float e0 = (v0 >= 0.0f) ? v0 : ALPHA * v0;
        float ex0 = __expf(e0);
        denom += ex0;
        if (lane == (k & 31)) g_att[start + k] = ex0;
    }
    const float inv = 1.0f / fmaxf(denom, EPS_RS);
    for (int t = lane; t < d; t += 32)
        g_att[start + t] *= inv;
}

// ---------------------------------------------------------------------------
// Kernel 7b: gather — R7 loop form deepened to 8 edges in flight
// ---------------------------------------------------------------------------
__device__ __forceinline__ void fma8_h(float* acc, uint4 v, float a) {
    float2 f;
    f = __half22float2(*(__half2*)&v.x);
    acc[0] = fmaf(a, f.x, acc[0]); acc[1] = fmaf(a, f.y, acc[1]);
    f = __half22float2(*((__half2*)&v.x + 1));
    acc[2] = fmaf(a, f.x, acc[2]); acc[3] = fmaf(a, f.y, acc[3]);
    f = __half22float2(*(__half2*)&v.z);
    acc[4] = fmaf(a, f.x, acc[4]); acc[5] = fmaf(a, f.y, acc[5]);
    f = __half22float2(*((__half2*)&v.z + 1));
    acc[6] = fmaf(a, f.x, acc[6]); acc[7] = fmaf(a, f.y, acc[7]);
}

__global__ __launch_bounds__(256) void k_gather(
    float* __restrict__ out,   // [N, 256]
    int n)
{
    const int w    = blockIdx.x * 8 + (threadIdx.x >> 5);
    const int lane = threadIdx.x & 31;
    if (w >= n) return;

    const int start = g_rowstart[w];
    const int d     = g_deg[w];
    const __half* base = g_Wh_h + lane * 8;   // 16B per lane, 512B per warp row

    float acc[8];
#pragma unroll
    for (int q = 0; q < 8; q++) acc[q] = 0.0f;

    int k = 0;
    for (; k + 7 < d; k += 8) {
        int   j[8];
        float a[8];
        uint4 v[8];
#pragma unroll
        for (int u = 0; u < 8; u++) j[u] = __ldg(g_edst + start + k + u);
#pragma unroll
        for (int u = 0; u < 8; u++) a[u] = __ldg(g_att + start + k + u);
#pragma unroll
        for (int u = 0; u < 8; u++)
            v[u] = __ldg((const uint4*)(base + (size_t)j[u] * OUT_F));
#pragma unroll
        for (int u = 0; u < 8; u++) fma8_h(acc, v[u], a[u]);
    }
    for (; k + 3 < d; k += 4) {
        int j0 = __ldg(g_edst + start + k);
        int j1 = __ldg(g_edst + start + k + 1);
        int j2 = __ldg(g_edst + start + k + 2);
        int j3 = __ldg(g_edst + start + k + 3);
        float a0 = __ldg(g_att + start + k);
        float a1 = __ldg(g_att + start + k + 1);
        float a2 = __ldg(g_att + start + k + 2);
        float a3 = __ldg(g_att + start + k + 3);
        uint4 v0 = __ldg((const uint4*)(base + (size_t)j0 * OUT_F));
        uint4 v1 = __ldg((const uint4*)(base + (size_t)j1 * OUT_F));
        uint4 v2 = __ldg((const uint4*)(base + (size_t)j2 * OUT_F));
        uint4 v3 = __ldg((const uint4*)(base + (size_t)j3 * OUT_F));
        fma8_h(acc, v0, a0);
        fma8_h(acc, v1, a1);
        fma8_h(acc, v2, a2);
        fma8_h(acc, v3, a3);
    }
    for (; k < d; k++) {
        int j0 = __ldg(g_edst + start + k);
        float a0 = __ldg(g_att + start + k);
        uint4 v0 = __ldg((const uint4*)(base + (size_t)j0 * OUT_F));
        fma8_h(acc, v0, a0);
    }

    float* o = out + (size_t)w * OUT_F + lane * 8;
    __stcs((float4*)(o + 0), make_float4(acc[0], acc[1], acc[2], acc[3]));
    __stcs((float4*)(o + 4), make_float4(acc[4], acc[5], acc[6], acc[7]));
}

// ---------------------------------------------------------------------------
// Launch — stream fork: branch A = prep_W + GEMM (default stream),
//                        branch B = CSR build + attention (s2), join -> gather
// ---------------------------------------------------------------------------
extern "C" void kernel_launch(void* const* d_in, const int* in_sizes, int n_in,
                              void* d_out, int out_size)
{
    const float* h     = (const float*)d_in[0];   // [N, 256] fp32
    const float* label = (const float*)d_in[1];   // [N, 32]  fp32
    const float* W     = (const float*)d_in[2];   // [256, 256] fp32
    const int*   adj   = (const int*)d_in[3];     // [2, E] int32
    float*       out   = (float*)d_out;

    const int N = in_sizes[0] / IN_F;      // 100000
    const int E = in_sizes[3] / 2;         // 1600000

    const int T = 256;
    const int gbN = (N + T - 1) / T;
    const int gbE = (E + T - 1) / T;

    static cudaStream_t s2 = nullptr;
    static cudaEvent_t  evF = nullptr, evJ = nullptr;
    if (s2 == nullptr) {
        cudaFuncSetAttribute(k_gemm_mma, cudaFuncAttributeMaxDynamicSharedMemorySize, GSM_TOTAL);
        cudaStreamCreateWithFlags(&s2, cudaStreamNonBlocking);
        cudaEventCreateWithFlags(&evF, cudaEventDisableTiming);
        cudaEventCreateWithFlags(&evJ, cudaEventDisableTiming);
    }

    // fork
    cudaEventRecord(evF, 0);
    cudaStreamWaitEvent(s2, evF, 0);

    // ---- branch B (s2): CSR build + attention weights
    k_zero_deg<<<gbN, T, 0, s2>>>(N);
    k_count<<<gbE, T, 0, s2>>>(adj, E);
    int nb = (N + SCAN_BLK - 1) / SCAN_BLK;
    k_scan1<<<nb, SCAN_BLK, 0, s2>>>(N);
    k_scan2<<<1, 256, 0, s2>>>(nb);
    k_scan3<<<gbN, T, 0, s2>>>(N);
    k_scatter<<<gbE, T, 0, s2>>>(adj, E);
    k_attention<<<(N + 7) / 8, 256, 0, s2>>>(label, N);
    cudaEventRecord(evJ, s2);

    // ---- branch A (default stream): GEMM (full-N CTA, A read once, fp16 1-product)
    k_prep_W<<<256, 256>>>(W);
    dim3 ggrid(1, (N + 127) / 128);
    k_gemm_mma<<<ggrid, 512, GSM_TOTAL>>>(h, N);

    // join, then gather
    cudaStreamWaitEvent(0, evJ, 0);
    k_gather<<<(N + 7) / 8, 256>>>(out, N);
}